// round 3
// baseline (speedup 1.0000x reference)
#include <cuda_runtime.h>

#define B_ROWS 8192
#define HDIM   1024
#define PCOLS  384     // [group0: rx|t00|t10 (192)] [group1: rx|t01|t11 (192)]
#define KV     192
#define NACC   2048

// ---------------- device scratch (no allocations allowed) ----------------
__device__ __align__(16) float g_P[B_ROWS * PCOLS];        // 12.6 MB
__device__ __align__(16) float g_V[2 * KV * NACC];         // 3.1 MB
__device__ __align__(16) float g_bias[4096];

// ---------------- helpers ----------------
__device__ __forceinline__ float tf32r(float x) {
    unsigned u; asm("cvt.rna.tf32.f32 %0, %1;" : "=r"(u) : "f"(x));
    return __uint_as_float(u);
}
__device__ __forceinline__ float sigmoid_f(float x) {
    float e; asm("ex2.approx.f32 %0, %1;" : "=f"(e) : "f"(-x * 1.4426950408889634f));
    float r; asm("rcp.approx.f32 %0, %1;" : "=f"(r) : "f"(1.0f + e));
    return r;
}
__device__ __forceinline__ float tanh_f(float x) {
    return fmaf(2.0f, sigmoid_f(2.0f * x), -1.0f);
}
__device__ __forceinline__ void mma_tf32(float* d, const unsigned* a, const unsigned* b) {
    asm volatile(
        "mma.sync.aligned.m16n8k8.row.col.f32.tf32.tf32.f32 "
        "{%0,%1,%2,%3}, {%4,%5,%6,%7}, {%8,%9}, {%0,%1,%2,%3};\n"
        : "+f"(d[0]), "+f"(d[1]), "+f"(d[2]), "+f"(d[3])
        : "r"(a[0]), "r"(a[1]), "r"(a[2]), "r"(a[3]), "r"(b[0]), "r"(b[1]));
}
__device__ __forceinline__ void cp_async16(float* dst, const float* src) {
    unsigned d = (unsigned)__cvta_generic_to_shared(dst);
    asm volatile("cp.async.cg.shared.global [%0], [%1], 16;" :: "r"(d), "l"(src));
}

// ---------------- prep: build V_g (192 x 2048, tf32-rounded) + combined bias ----------------
__global__ void prep_kernel(const float* __restrict__ v_x, const float* __restrict__ v_h0,
                            const float* __restrict__ v_h1, const float* __restrict__ bx,
                            const float* __restrict__ bh) {
    int idx = blockIdx.x * 256 + threadIdx.x;
    if (idx < 4096) g_bias[idx] = bx[idx] + bh[idx];
    int total = 2 * KV * NACC;
    if (idx >= total) return;
    int k = idx & (NACC - 1);
    int r = (idx / NACC) % KV;
    int g = idx / (NACC * KV);
    float val;
    if (r < 64) {
        int n = (k >> 9) * 1024 + g * 512 + (k & 511);   // gate*1024 + g*512 + s
        val = v_x[n * 64 + r];
    } else if (r < 128) {
        val = v_h0[(g * 64 + (r - 64)) * 2048 + k];
    } else {
        val = v_h1[(g * 64 + (r - 128)) * 2048 + k];
    }
    g_V[idx] = tf32r(val);
}

// ---------------- stage 1: P = structured low-rank projections (tf32 MMA) ----------------
#define S1_LDA 20
#define S1_LDW 68
__global__ __launch_bounds__(128) void stage1_kernel(
    const float* __restrict__ x, const float* __restrict__ h,
    const float* __restrict__ u_x, const float* __restrict__ u_h0,
    const float* __restrict__ u_h1) {
    __shared__ float As[128 * S1_LDA];
    __shared__ float Ws[16 * S1_LDW];

    int blk = blockIdx.y;
    int r0  = blockIdx.x * 128;
    const float* Aptr; const float* Wptr; int K; int pcol;
    if      (blk == 0) { Aptr = x;       Wptr = u_x;            K = 1024; pcol = 0;   }
    else if (blk == 1) { Aptr = h;       Wptr = u_h0;           K = 512;  pcol = 64;  }  // t_{0,0}
    else if (blk == 2) { Aptr = h + 512; Wptr = u_h1;           K = 512;  pcol = 128; }  // t_{1,0} (perm)
    else if (blk == 3) { Aptr = h + 512; Wptr = u_h0 + 512*64;  K = 512;  pcol = 256; }  // t_{0,1} (perm)
    else               { Aptr = h;       Wptr = u_h1 + 512*64;  K = 512;  pcol = 320; }  // t_{1,1}

    int t = threadIdx.x;
    int warp = t >> 5, lane = t & 31, g4 = lane >> 2, q = lane & 3;

    float acc[2][8][4];
#pragma unroll
    for (int i = 0; i < 2; i++)
#pragma unroll
        for (int j = 0; j < 8; j++)
#pragma unroll
            for (int l = 0; l < 4; l++) acc[i][j][l] = 0.f;

    int NK = K >> 4;
    float4 aR[4], wR[2];
    {   // prefetch chunk 0
        const float* arow = Aptr + (size_t)(r0 + t) * 1024;
        aR[0] = *(const float4*)(arow + 0);  aR[1] = *(const float4*)(arow + 4);
        aR[2] = *(const float4*)(arow + 8);  aR[3] = *(const float4*)(arow + 12);
        wR[0] = *(const float4*)(Wptr + ((t >> 4)    ) * 64 + (t & 15) * 4);
        wR[1] = *(const float4*)(Wptr + ((t >> 4) + 8) * 64 + (t & 15) * 4);
    }

#pragma unroll 1
    for (int ks = 0; ks < NK; ks++) {
        __syncthreads();
        {   // store prefetched chunk to smem with tf32 rounding
            float* ad = &As[t * S1_LDA];
            ad[0]  = tf32r(aR[0].x); ad[1]  = tf32r(aR[0].y); ad[2]  = tf32r(aR[0].z); ad[3]  = tf32r(aR[0].w);
            ad[4]  = tf32r(aR[1].x); ad[5]  = tf32r(aR[1].y); ad[6]  = tf32r(aR[1].z); ad[7]  = tf32r(aR[1].w);
            ad[8]  = tf32r(aR[2].x); ad[9]  = tf32r(aR[2].y); ad[10] = tf32r(aR[2].z); ad[11] = tf32r(aR[2].w);
            ad[12] = tf32r(aR[3].x); ad[13] = tf32r(aR[3].y); ad[14] = tf32r(aR[3].z); ad[15] = tf32r(aR[3].w);
            int wr = t >> 4, wc = (t & 15) * 4;
            float* w0 = &Ws[wr * S1_LDW + wc];
            w0[0] = tf32r(wR[0].x); w0[1] = tf32r(wR[0].y); w0[2] = tf32r(wR[0].z); w0[3] = tf32r(wR[0].w);
            float* w1 = &Ws[(wr + 8) * S1_LDW + wc];
            w1[0] = tf32r(wR[1].x); w1[1] = tf32r(wR[1].y); w1[2] = tf32r(wR[1].z); w1[3] = tf32r(wR[1].w);
        }
        __syncthreads();
        if (ks + 1 < NK) {
            int koff = (ks + 1) << 4;
            const float* arow = Aptr + (size_t)(r0 + t) * 1024 + koff;
            aR[0] = *(const float4*)(arow + 0);  aR[1] = *(const float4*)(arow + 4);
            aR[2] = *(const float4*)(arow + 8);  aR[3] = *(const float4*)(arow + 12);
            wR[0] = *(const float4*)(Wptr + (koff + (t >> 4)    ) * 64 + (t & 15) * 4);
            wR[1] = *(const float4*)(Wptr + (koff + (t >> 4) + 8) * 64 + (t & 15) * 4);
        }
#pragma unroll
        for (int kk = 0; kk < 2; kk++) {
            int kb = kk * 8;
            unsigned af[2][4], bf[8][2];
#pragma unroll
            for (int mt = 0; mt < 2; mt++) {
                int rr = warp * 32 + mt * 16 + g4;
                af[mt][0] = __float_as_uint(As[rr * S1_LDA + kb + q]);
                af[mt][1] = __float_as_uint(As[(rr + 8) * S1_LDA + kb + q]);
                af[mt][2] = __float_as_uint(As[rr * S1_LDA + kb + q + 4]);
                af[mt][3] = __float_as_uint(As[(rr + 8) * S1_LDA + kb + q + 4]);
            }
#pragma unroll
            for (int nt = 0; nt < 8; nt++) {
                bf[nt][0] = __float_as_uint(Ws[(kb + q) * S1_LDW + nt * 8 + g4]);
                bf[nt][1] = __float_as_uint(Ws[(kb + q + 4) * S1_LDW + nt * 8 + g4]);
            }
#pragma unroll
            for (int mt = 0; mt < 2; mt++)
#pragma unroll
                for (int nt = 0; nt < 8; nt++)
                    mma_tf32(acc[mt][nt], af[mt], bf[nt]);
        }
    }

    // store P (tf32-rounded so stage-2 operands are exact-representable)
#pragma unroll
    for (int mt = 0; mt < 2; mt++) {
        int rr = r0 + warp * 32 + mt * 16 + g4;
#pragma unroll
        for (int nt = 0; nt < 8; nt++) {
            int col = pcol + nt * 8 + 2 * q;
            float2 v0 = make_float2(tf32r(acc[mt][nt][0]), tf32r(acc[mt][nt][1]));
            float2 v1 = make_float2(tf32r(acc[mt][nt][2]), tf32r(acc[mt][nt][3]));
            *(float2*)&g_P[(size_t)rr * PCOLS + col] = v0;
            *(float2*)&g_P[(size_t)(rr + 8) * PCOLS + col] = v1;
            if (blk == 0) {  // rx duplicated into group-1 feature block
                *(float2*)&g_P[(size_t)rr * PCOLS + col + 192] = v0;
                *(float2*)&g_P[(size_t)(rr + 8) * PCOLS + col + 192] = v1;
            }
        }
    }
}

// ---------------- stage 2: preact = P_g @ V_g, fused gate epilogue ----------------
#define S2_LDA 20
#define S2_LDB 260
#define S2_SMEM ((2 * 128 * S2_LDA + 2 * 16 * S2_LDB) * 4)

__global__ __launch_bounds__(256) void stage2_kernel(const float* __restrict__ cin,
                                                     float* __restrict__ out) {
    extern __shared__ float sm[];
    float* Abuf = sm;                       // 2 * 128*20
    float* Bbuf = sm + 2 * 128 * S2_LDA;    // 2 * 16*260

    int r0 = blockIdx.x * 128;
    int s0 = blockIdx.y * 64;
    int g  = blockIdx.z;
    int t = threadIdx.x;
    int warp = t >> 5, lane = t & 31, g4 = lane >> 2, q = lane & 3;
    int wm = warp >> 2, wn = warp & 3;

    const float* Pbase = g_P + g * 192;
    const float* Vbase = g_V + (size_t)g * KV * NACC;

    float acc[4][8][4];
#pragma unroll
    for (int i = 0; i < 4; i++)
#pragma unroll
        for (int j = 0; j < 8; j++)
#pragma unroll
            for (int l = 0; l < 4; l++) acc[i][j][l] = 0.f;

    // B column permutation: cc -> k_global = gate*512 + (s0 + warp_n*16 + u)
    auto issue = [&](int ks, int buf) {
        int k0 = ks * 16;
        float* Ad = Abuf + buf * 128 * S2_LDA;
        float* Bd = Bbuf + buf * 16 * S2_LDB;
#pragma unroll
        for (int i = 0; i < 2; i++) {
            int idx = t + i * 256;
            int row = idx >> 2, qq = idx & 3;
            cp_async16(&Ad[row * S2_LDA + qq * 4],
                       Pbase + (size_t)(r0 + row) * PCOLS + k0 + qq * 4);
        }
#pragma unroll
        for (int i = 0; i < 4; i++) {
            int idx = t + i * 256;
            int k = idx >> 6; int rem = idx & 63; int w = rem >> 2; int qq = rem & 3;
            int kcol = (w & 3) * 512 + s0 + ((w >> 2) << 4) + qq * 4;
            cp_async16(&Bd[k * S2_LDB + w * 16 + qq * 4],
                       Vbase + (size_t)(k0 + k) * NACC + kcol);
        }
        asm volatile("cp.async.commit_group;");
    };

    issue(0, 0);
    int buf = 0;
#pragma unroll 1
    for (int ks = 0; ks < 12; ks++) {
        if (ks + 1 < 12) {
            issue(ks + 1, buf ^ 1);
            asm volatile("cp.async.wait_group 1;");
        } else {
            asm volatile("cp.async.wait_group 0;");
        }
        __syncthreads();
        float* Aa = Abuf + buf * 128 * S2_LDA;
        float* Bb = Bbuf + buf * 16 * S2_LDB;
#pragma unroll
        for (int kk = 0; kk < 2; kk++) {
            int kb = kk * 8;
            unsigned af[4][4], bf[8][2];
#pragma unroll
            for (int mt = 0; mt < 4; mt++) {
                int rr = wm * 64 + mt * 16 + g4;
                af[mt][0] = __float_as_uint(Aa[rr * S2_LDA + kb + q]);
                af[mt][1] = __float_as_uint(Aa[(rr + 8) * S2_LDA + kb + q]);
                af[mt][2] = __float_as_uint(Aa[rr * S2_LDA + kb + q + 4]);
                af[mt][3] = __float_as_uint(Aa[(rr + 8) * S2_LDA + kb + q + 4]);
            }
#pragma unroll
            for (int nt = 0; nt < 8; nt++) {
                int cc = wn * 64 + nt * 8 + g4;
                bf[nt][0] = __float_as_uint(Bb[(kb + q) * S2_LDB + cc]);
                bf[nt][1] = __float_as_uint(Bb[(kb + q + 4) * S2_LDB + cc]);
            }
#pragma unroll
            for (int mt = 0; mt < 4; mt++)
#pragma unroll
                for (int nt = 0; nt < 8; nt++)
                    mma_tf32(acc[mt][nt], af[mt], bf[nt]);
        }
        __syncthreads();
        buf ^= 1;
    }

    // fused epilogue: per thread, all 4 gates of each (row, s) live in its own regs
    float* out_h = out;
    float* out_c = out + (size_t)B_ROWS * HDIM;
    int sbase = s0 + wn * 16;
#pragma unroll
    for (int mt = 0; mt < 4; mt++) {
#pragma unroll
        for (int rh = 0; rh < 2; rh++) {
            int row = r0 + wm * 64 + mt * 16 + g4 + rh * 8;
#pragma unroll
            for (int hi = 0; hi < 2; hi++) {
                float hv2[2], cv2[2];
#pragma unroll
                for (int e = 0; e < 2; e++) {
                    int s = sbase + hi * 8 + 2 * q + e;
                    int ridx = rh * 2 + e;
                    float fp = acc[mt][0 + hi][ridx] + g_bias[0 * 1024 + g * 512 + s];
                    float ip = acc[mt][2 + hi][ridx] + g_bias[1 * 1024 + g * 512 + s];
                    float np = acc[mt][4 + hi][ridx] + g_bias[2 * 1024 + g * 512 + s];
                    float op = acc[mt][6 + hi][ridx] + g_bias[3 * 1024 + g * 512 + s];
                    float cv = cin[(size_t)row * HDIM + g * 512 + s];
                    float fg = sigmoid_f(fp), ig = sigmoid_f(ip), og = sigmoid_f(op);
                    float ng = tanh_f(np);
                    float cn = fg * cv + ig * ng;
                    float hn = og * tanh_f(cn);
                    hv2[e] = hn; cv2[e] = cn;
                }
                size_t off = (size_t)row * HDIM + g * 512 + sbase + hi * 8 + 2 * q;
                *(float2*)&out_h[off] = make_float2(hv2[0], hv2[1]);
                *(float2*)&out_c[off] = make_float2(cv2[0], cv2[1]);
            }
        }
    }
}

// ---------------- launch ----------------
extern "C" void kernel_launch(void* const* d_in, const int* in_sizes, int n_in,
                              void* d_out, int out_size) {
    const float* x    = (const float*)d_in[0];
    const float* h    = (const float*)d_in[1];
    const float* c    = (const float*)d_in[2];
    const float* u_x  = (const float*)d_in[3];
    const float* v_x  = (const float*)d_in[4];
    const float* u_h0 = (const float*)d_in[5];
    const float* v_h0 = (const float*)d_in[6];
    const float* u_h1 = (const float*)d_in[7];
    const float* v_h1 = (const float*)d_in[8];
    const float* bx   = (const float*)d_in[9];
    const float* bh   = (const float*)d_in[10];

    cudaFuncSetAttribute(stage2_kernel, cudaFuncAttributeMaxDynamicSharedMemorySize, S2_SMEM);

    prep_kernel<<<(2 * KV * NACC + 255) / 256, 256>>>(v_x, v_h0, v_h1, bx, bh);
    stage1_kernel<<<dim3(64, 5), 128>>>(x, h, u_x, u_h0, u_h1);
    stage2_kernel<<<dim3(64, 8, 2), 256, S2_SMEM>>>(c, (float*)d_out);
}

// round 8
// speedup vs baseline: 1.0909x; 1.0909x over previous
#include <cuda_runtime.h>

#define B_ROWS 8192
#define HDIM   1024
#define PCOLS  384     // [group0: rx|t00|t10 (192)] [group1: rx|t01|t11 (192)]
#define KV     192
#define NACC   2048

// ---------------- device scratch (no allocations allowed) ----------------
__device__ __align__(1024) float g_P[B_ROWS * PCOLS];        // 12.6 MB
__device__ __align__(1024) float g_V[2 * KV * NACC];         // 3.1 MB  [g][k][n]
__device__ __align__(16)   float g_bias[4096];

// ---------------- helpers ----------------
__device__ __forceinline__ float tf32r(float x) {
    unsigned u; asm("cvt.rna.tf32.f32 %0, %1;" : "=r"(u) : "f"(x));
    return __uint_as_float(u);
}
__device__ __forceinline__ float sigmoid_f(float x) {
    float e; asm("ex2.approx.f32 %0, %1;" : "=f"(e) : "f"(-x * 1.4426950408889634f));
    float r; asm("rcp.approx.f32 %0, %1;" : "=f"(r) : "f"(1.0f + e));
    return r;
}
__device__ __forceinline__ float tanh_f(float x) {
    return fmaf(2.0f, sigmoid_f(2.0f * x), -1.0f);
}
__device__ __forceinline__ void mma_tf32(float* d, const unsigned* a, const unsigned* b) {
    asm volatile(
        "mma.sync.aligned.m16n8k8.row.col.f32.tf32.tf32.f32 "
        "{%0,%1,%2,%3}, {%4,%5,%6,%7}, {%8,%9}, {%0,%1,%2,%3};\n"
        : "+f"(d[0]), "+f"(d[1]), "+f"(d[2]), "+f"(d[3])
        : "r"(a[0]), "r"(a[1]), "r"(a[2]), "r"(a[3]), "r"(b[0]), "r"(b[1]));
}
__device__ __forceinline__ void cp_async16(float* dst, const float* src) {
    unsigned d = (unsigned)__cvta_generic_to_shared(dst);
    asm volatile("cp.async.cg.shared.global [%0], [%1], 16;" :: "r"(d), "l"(src));
}

// ---------------- prep: build V_g (192 x 2048, tf32-rounded, [g][k][n]) + combined bias ----------------
__global__ void prep_kernel(const float* __restrict__ v_x, const float* __restrict__ v_h0,
                            const float* __restrict__ v_h1, const float* __restrict__ bx,
                            const float* __restrict__ bh) {
    int idx = blockIdx.x * 256 + threadIdx.x;
    if (idx < 4096) g_bias[idx] = bx[idx] + bh[idx];
    int total = 2 * KV * NACC;
    if (idx >= total) return;
    int k = idx & (NACC - 1);            // n-col: gate*512 + s  (per group)
    int r = (idx / NACC) % KV;           // K index
    int g = idx / (NACC * KV);
    float val;
    if (r < 64) {
        int n = (k >> 9) * 1024 + g * 512 + (k & 511);   // gate*1024 + g*512 + s
        val = v_x[n * 64 + r];
    } else if (r < 128) {
        int gate = k >> 9, s = k & 511;
        val = v_h0[(g * 64 + (r - 64)) * 2048 + gate * 512 + s];
    } else {
        int gate = k >> 9, s = k & 511;
        val = v_h1[(g * 64 + (r - 128)) * 2048 + gate * 512 + s];
    }
    g_V[idx] = tf32r(val);
}

// ---------------- stage 1: P = structured low-rank projections (tf32 MMA) ----------------
#define S1_LDA 20
#define S1_LDW 68
__global__ __launch_bounds__(128) void stage1_kernel(
    const float* __restrict__ x, const float* __restrict__ h,
    const float* __restrict__ u_x, const float* __restrict__ u_h0,
    const float* __restrict__ u_h1) {
    __shared__ float As[128 * S1_LDA];
    __shared__ float Ws[16 * S1_LDW];

    int blk = blockIdx.y;
    int r0  = blockIdx.x * 128;
    const float* Aptr; const float* Wptr; int K; int pcol;
    if      (blk == 0) { Aptr = x;       Wptr = u_x;            K = 1024; pcol = 0;   }
    else if (blk == 1) { Aptr = h;       Wptr = u_h0;           K = 512;  pcol = 64;  }
    else if (blk == 2) { Aptr = h + 512; Wptr = u_h1;           K = 512;  pcol = 128; }
    else if (blk == 3) { Aptr = h + 512; Wptr = u_h0 + 512*64;  K = 512;  pcol = 256; }
    else               { Aptr = h;       Wptr = u_h1 + 512*64;  K = 512;  pcol = 320; }

    int t = threadIdx.x;
    int warp = t >> 5, lane = t & 31, g4 = lane >> 2, q = lane & 3;

    float acc[2][8][4];
#pragma unroll
    for (int i = 0; i < 2; i++)
#pragma unroll
        for (int j = 0; j < 8; j++)
#pragma unroll
            for (int l = 0; l < 4; l++) acc[i][j][l] = 0.f;

    int NK = K >> 4;
    float4 aR[4], wR[2];
    {
        const float* arow = Aptr + (size_t)(r0 + t) * 1024;
        aR[0] = *(const float4*)(arow + 0);  aR[1] = *(const float4*)(arow + 4);
        aR[2] = *(const float4*)(arow + 8);  aR[3] = *(const float4*)(arow + 12);
        wR[0] = *(const float4*)(Wptr + ((t >> 4)    ) * 64 + (t & 15) * 4);
        wR[1] = *(const float4*)(Wptr + ((t >> 4) + 8) * 64 + (t & 15) * 4);
    }

#pragma unroll 1
    for (int ks = 0; ks < NK; ks++) {
        __syncthreads();
        {
            float* ad = &As[t * S1_LDA];
            ad[0]  = tf32r(aR[0].x); ad[1]  = tf32r(aR[0].y); ad[2]  = tf32r(aR[0].z); ad[3]  = tf32r(aR[0].w);
            ad[4]  = tf32r(aR[1].x); ad[5]  = tf32r(aR[1].y); ad[6]  = tf32r(aR[1].z); ad[7]  = tf32r(aR[1].w);
            ad[8]  = tf32r(aR[2].x); ad[9]  = tf32r(aR[2].y); ad[10] = tf32r(aR[2].z); ad[11] = tf32r(aR[2].w);
            ad[12] = tf32r(aR[3].x); ad[13] = tf32r(aR[3].y); ad[14] = tf32r(aR[3].z); ad[15] = tf32r(aR[3].w);
            int wr = t >> 4, wc = (t & 15) * 4;
            float* w0 = &Ws[wr * S1_LDW + wc];
            w0[0] = tf32r(wR[0].x); w0[1] = tf32r(wR[0].y); w0[2] = tf32r(wR[0].z); w0[3] = tf32r(wR[0].w);
            float* w1 = &Ws[(wr + 8) * S1_LDW + wc];
            w1[0] = tf32r(wR[1].x); w1[1] = tf32r(wR[1].y); w1[2] = tf32r(wR[1].z); w1[3] = tf32r(wR[1].w);
        }
        __syncthreads();
        if (ks + 1 < NK) {
            int koff = (ks + 1) << 4;
            const float* arow = Aptr + (size_t)(r0 + t) * 1024 + koff;
            aR[0] = *(const float4*)(arow + 0);  aR[1] = *(const float4*)(arow + 4);
            aR[2] = *(const float4*)(arow + 8);  aR[3] = *(const float4*)(arow + 12);
            wR[0] = *(const float4*)(Wptr + (koff + (t >> 4)    ) * 64 + (t & 15) * 4);
            wR[1] = *(const float4*)(Wptr + (koff + (t >> 4) + 8) * 64 + (t & 15) * 4);
        }
#pragma unroll
        for (int kk = 0; kk < 2; kk++) {
            int kb = kk * 8;
            unsigned af[2][4], bf[8][2];
#pragma unroll
            for (int mt = 0; mt < 2; mt++) {
                int rr = warp * 32 + mt * 16 + g4;
                af[mt][0] = __float_as_uint(As[rr * S1_LDA + kb + q]);
                af[mt][1] = __float_as_uint(As[(rr + 8) * S1_LDA + kb + q]);
                af[mt][2] = __float_as_uint(As[rr * S1_LDA + kb + q + 4]);
                af[mt][3] = __float_as_uint(As[(rr + 8) * S1_LDA + kb + q + 4]);
            }
#pragma unroll
            for (int nt = 0; nt < 8; nt++) {
                bf[nt][0] = __float_as_uint(Ws[(kb + q) * S1_LDW + nt * 8 + g4]);
                bf[nt][1] = __float_as_uint(Ws[(kb + q + 4) * S1_LDW + nt * 8 + g4]);
            }
#pragma unroll
            for (int mt = 0; mt < 2; mt++)
#pragma unroll
                for (int nt = 0; nt < 8; nt++)
                    mma_tf32(acc[mt][nt], af[mt], bf[nt]);
        }
    }

#pragma unroll
    for (int mt = 0; mt < 2; mt++) {
        int rr = r0 + warp * 32 + mt * 16 + g4;
#pragma unroll
        for (int nt = 0; nt < 8; nt++) {
            int col = pcol + nt * 8 + 2 * q;
            float2 v0 = make_float2(tf32r(acc[mt][nt][0]), tf32r(acc[mt][nt][1]));
            float2 v1 = make_float2(tf32r(acc[mt][nt][2]), tf32r(acc[mt][nt][3]));
            *(float2*)&g_P[(size_t)rr * PCOLS + col] = v0;
            *(float2*)&g_P[(size_t)(rr + 8) * PCOLS + col] = v1;
            if (blk == 0) {
                *(float2*)&g_P[(size_t)rr * PCOLS + col + 192] = v0;
                *(float2*)&g_P[(size_t)(rr + 8) * PCOLS + col + 192] = v1;
            }
        }
    }
}

// ---------------- stage 2: 128x128 tile, 4-stage cp.async, occupancy 2, fused epilogue ----------------
// Per stage: A 128x16 (lda 20) = 2560 floats, B 16x128 (ldb 132) = 2112 floats.
#define S2_LDA   20
#define S2_LDB   132
#define S2_STG   (128 * S2_LDA + 16 * S2_LDB)     // floats per stage = 4672
#define S2_DSMEM (4 * S2_STG * 4)                 // 74752 bytes
#define S2_NCH   12                               // 192 / 16

__global__ __launch_bounds__(256, 2) void stage2_kernel(const float* __restrict__ cin,
                                                        float* __restrict__ out) {
    extern __shared__ float sm[];

    int r0 = blockIdx.x * 128;
    int s0 = blockIdx.y * 32;           // 32 s-values -> 128 n-cols
    int g  = blockIdx.z;
    int t = threadIdx.x;
    int warp = t >> 5, lane = t & 31, g4 = lane >> 2, q = lane & 3;
    int wm = warp & 3, wn = warp >> 2;  // 4 m-warps x 2 n-warps; warp tile 32x64

    const float* Pbase = g_P + (size_t)r0 * PCOLS + g * 192;
    const float* Vbase = g_V + (size_t)g * KV * NACC;

    float acc[2][8][4];
#pragma unroll
    for (int i = 0; i < 2; i++)
#pragma unroll
        for (int j = 0; j < 8; j++)
#pragma unroll
            for (int l = 0; l < 4; l++) acc[i][j][l] = 0.f;

    // B smem column permutation (within each 64-col warp half): c = gate*16 + s_local
    auto issue = [&](int c) {
        if (c < S2_NCH) {
            int k0 = c * 16;
            float* Ad = sm + (c & 3) * S2_STG;
            float* Bd = Ad + 128 * S2_LDA;
            // A: 128 rows x 4 segs = 512 segs, 2 per thread
#pragma unroll
            for (int i = 0; i < 2; i++) {
                int idx = t + i * 256;
                int row = idx >> 2, seg = idx & 3;
                cp_async16(&Ad[row * S2_LDA + seg * 4],
                           Pbase + (size_t)row * PCOLS + k0 + seg * 4);
            }
            // B: 16 k-rows x 32 segs = 512 segs, 2 per thread
#pragma unroll
            for (int i = 0; i < 2; i++) {
                int idx = t + i * 256;
                int k = idx >> 5, segn = idx & 31;
                int half = segn >> 4;                 // which 64-col warp half
                int gate = (segn & 15) >> 2;
                int sl   = (segn & 3) * 4;
                int ncol = gate * 512 + s0 + half * 16 + sl;
                cp_async16(&Bd[k * S2_LDB + segn * 4],
                           Vbase + (size_t)(k0 + k) * NACC + ncol);
            }
        }
        asm volatile("cp.async.commit_group;" ::: "memory");
    };

    issue(0); issue(1); issue(2);

#pragma unroll 1
    for (int c = 0; c < S2_NCH; c++) {
        asm volatile("cp.async.wait_group 2;" ::: "memory");
        __syncthreads();
        float* Aa = sm + (c & 3) * S2_STG;
        float* Bb = Aa + 128 * S2_LDA;
#pragma unroll
        for (int kk = 0; kk < 2; kk++) {
            int kb = kk * 8;
            unsigned af[2][4], bf[8][2];
#pragma unroll
            for (int mt = 0; mt < 2; mt++) {
                int rr = wm * 32 + mt * 16 + g4;
                af[mt][0] = __float_as_uint(Aa[rr * S2_LDA + kb + q]);
                af[mt][1] = __float_as_uint(Aa[(rr + 8) * S2_LDA + kb + q]);
                af[mt][2] = __float_as_uint(Aa[rr * S2_LDA + kb + q + 4]);
                af[mt][3] = __float_as_uint(Aa[(rr + 8) * S2_LDA + kb + q + 4]);
            }
#pragma unroll
            for (int nt = 0; nt < 8; nt++) {
                int cc = wn * 64 + nt * 8 + g4;
                bf[nt][0] = __float_as_uint(Bb[(kb + q) * S2_LDB + cc]);
                bf[nt][1] = __float_as_uint(Bb[(kb + q + 4) * S2_LDB + cc]);
            }
#pragma unroll
            for (int mt = 0; mt < 2; mt++)
#pragma unroll
                for (int nt = 0; nt < 8; nt++)
                    mma_tf32(acc[mt][nt], af[mt], bf[nt]);
        }
        issue(c + 3);
    }

    // ---- fused epilogue: thread col p = wn*64 + nt*8 + 2q + e; gate = nt>>1,
    //      s = s0 + wn*16 + (nt&1)*8 + 2q + e  -> all 4 gates live in-thread.
    float* out_h = out;
    float* out_c = out + (size_t)B_ROWS * HDIM;
#pragma unroll
    for (int mt = 0; mt < 2; mt++) {
#pragma unroll
        for (int rh = 0; rh < 2; rh++) {
            int row = r0 + wm * 32 + mt * 16 + g4 + rh * 8;
#pragma unroll
            for (int sh = 0; sh < 2; sh++) {
                int sbase = s0 + wn * 16 + sh * 8 + 2 * q;
                float hv2[2], cv2[2];
                float2 cvv = *(const float2*)&cin[(size_t)row * HDIM + g * 512 + sbase];
                float cvin[2] = { cvv.x, cvv.y };
#pragma unroll
                for (int e = 0; e < 2; e++) {
                    int s = sbase + e;
                    int l = rh * 2 + e;
                    float fp = acc[mt][0 + sh][l] + g_bias[0 * 1024 + g * 512 + s];
                    float ip = acc[mt][2 + sh][l] + g_bias[1 * 1024 + g * 512 + s];
                    float np = acc[mt][4 + sh][l] + g_bias[2 * 1024 + g * 512 + s];
                    float op = acc[mt][6 + sh][l] + g_bias[3 * 1024 + g * 512 + s];
                    float fg = sigmoid_f(fp), ig = sigmoid_f(ip), og = sigmoid_f(op);
                    float ng = tanh_f(np);
                    float cn = fg * cvin[e] + ig * ng;
                    hv2[e] = og * tanh_f(cn);
                    cv2[e] = cn;
                }
                size_t off = (size_t)row * HDIM + g * 512 + sbase;
                *(float2*)&out_h[off] = make_float2(hv2[0], hv2[1]);
                *(float2*)&out_c[off] = make_float2(cv2[0], cv2[1]);
            }
        }
    }
}

// ---------------- launch ----------------
extern "C" void kernel_launch(void* const* d_in, const int* in_sizes, int n_in,
                              void* d_out, int out_size) {
    const float* x    = (const float*)d_in[0];
    const float* h    = (const float*)d_in[1];
    const float* c    = (const float*)d_in[2];
    const float* u_x  = (const float*)d_in[3];
    const float* v_x  = (const float*)d_in[4];
    const float* u_h0 = (const float*)d_in[5];
    const float* v_h0 = (const float*)d_in[6];
    const float* u_h1 = (const float*)d_in[7];
    const float* v_h1 = (const float*)d_in[8];
    const float* bx   = (const float*)d_in[9];
    const float* bh   = (const float*)d_in[10];

    cudaFuncSetAttribute(stage2_kernel, cudaFuncAttributeMaxDynamicSharedMemorySize, S2_DSMEM);

    prep_kernel<<<(2 * KV * NACC + 255) / 256, 256>>>(v_x, v_h0, v_h1, bx, bh);
    stage1_kernel<<<dim3(64, 5), 128>>>(x, h, u_x, u_h0, u_h1);
    stage2_kernel<<<dim3(64, 16, 2), 256, S2_DSMEM>>>(c, (float*)d_out);
}

// round 9
// speedup vs baseline: 1.5186x; 1.3921x over previous
#include <cuda_runtime.h>
#include <cuda_fp16.h>

#define B_ROWS 8192
#define HDIM   1024
#define PCOLS  384
#define KV     192
#define NACC   2048

// ---------------- device scratch (no allocations allowed) ----------------
// g_Pf: A-fragment-ordered half2 P.  uint idx = ((row16*24 + slice16)*32 + lane)*4 + reg
//   reg: 0={A[g4][2q],[2q+1]}, 1={A[g4+8][2q..]}, 2={A[g4][2q+8..]}, 3={A[g4+8][2q+8..]}
__device__ __align__(1024) unsigned g_Pf[512 * 24 * 128];          // 6.3 MB
// g_Vf: B-fragment-ordered half2 V.  uint idx = (((g*16+n128)*12 + k16)*2 + wn)*512 + vg*128 + lane*4 + j
//   reg r = vg*4+j: nt = r>>1, kreg = r&1;  half pair = {B[k][n], B[k+1][n]},
//   k = k16*16 + 2q + kreg*8,  n(gate,s): gate = nt>>1, s = n128*32 + wn*16 + (nt&1)*8 + g4
__device__ __align__(1024) unsigned g_Vf[2 * 16 * 12 * 1024];      // 1.57 MB
__device__ __align__(16)   float g_bias[4096];

// ---------------- helpers ----------------
__device__ __forceinline__ float tf32r(float x) {
    unsigned u; asm("cvt.rna.tf32.f32 %0, %1;" : "=r"(u) : "f"(x));
    return __uint_as_float(u);
}
__device__ __forceinline__ unsigned pack_h2(float a, float b) {
    __half2 h = __floats2half2_rn(a, b);
    return *reinterpret_cast<unsigned*>(&h);
}
__device__ __forceinline__ float sigmoid_f(float x) {
    float e; asm("ex2.approx.f32 %0, %1;" : "=f"(e) : "f"(-x * 1.4426950408889634f));
    float r; asm("rcp.approx.f32 %0, %1;" : "=f"(r) : "f"(1.0f + e));
    return r;
}
__device__ __forceinline__ float tanh_f(float x) {
    return fmaf(2.0f, sigmoid_f(2.0f * x), -1.0f);
}
__device__ __forceinline__ void mma_tf32(float* d, const unsigned* a, const unsigned* b) {
    asm volatile(
        "mma.sync.aligned.m16n8k8.row.col.f32.tf32.tf32.f32 "
        "{%0,%1,%2,%3}, {%4,%5,%6,%7}, {%8,%9}, {%0,%1,%2,%3};\n"
        : "+f"(d[0]), "+f"(d[1]), "+f"(d[2]), "+f"(d[3])
        : "r"(a[0]), "r"(a[1]), "r"(a[2]), "r"(a[3]), "r"(b[0]), "r"(b[1]));
}
__device__ __forceinline__ void mma_f16(float* d, const unsigned* a, const unsigned* b) {
    asm volatile(
        "mma.sync.aligned.m16n8k16.row.col.f32.f16.f16.f32 "
        "{%0,%1,%2,%3}, {%4,%5,%6,%7}, {%8,%9}, {%0,%1,%2,%3};\n"
        : "+f"(d[0]), "+f"(d[1]), "+f"(d[2]), "+f"(d[3])
        : "r"(a[0]), "r"(a[1]), "r"(a[2]), "r"(a[3]), "r"(b[0]), "r"(b[1]));
}
__device__ __forceinline__ void cp_async16u(unsigned* dst, const unsigned* src) {
    unsigned d = (unsigned)__cvta_generic_to_shared(dst);
    asm volatile("cp.async.cg.shared.global [%0], [%1], 16;" :: "r"(d), "l"(src));
}

// ---------------- prep: build g_Vf (B-fragment-ordered half2) + combined bias ----------------
__global__ void prep_kernel(const float* __restrict__ v_x, const float* __restrict__ v_h0,
                            const float* __restrict__ v_h1, const float* __restrict__ bx,
                            const float* __restrict__ bh) {
    int idx = blockIdx.x * 256 + threadIdx.x;
    if (idx < 4096) g_bias[idx] = bx[idx] + bh[idx];
    if (idx >= 2 * 16 * 12 * 1024) return;

    int j    = idx & 3;
    int lane = (idx >> 2) & 31;
    int vg   = (idx >> 7) & 3;
    int rest = idx >> 9;
    int wn   = rest & 1;  rest >>= 1;
    int k16  = rest % 12; rest /= 12;
    int n128 = rest & 15;
    int g    = rest >> 4;

    int r    = vg * 4 + j;
    int nt   = r >> 1, kreg = r & 1;
    int g4   = lane >> 2, q = lane & 3;
    int k0   = k16 * 16 + 2 * q + kreg * 8;
    int gate = nt >> 1;
    int s    = n128 * 32 + wn * 16 + (nt & 1) * 8 + g4;

    float v[2];
#pragma unroll
    for (int e = 0; e < 2; e++) {
        int k = k0 + e;
        if (k < 64)       v[e] = v_x[(gate * 1024 + g * 512 + s) * 64 + k];
        else if (k < 128) v[e] = v_h0[(g * 64 + (k - 64)) * 2048 + gate * 512 + s];
        else              v[e] = v_h1[(g * 64 + (k - 128)) * 2048 + gate * 512 + s];
    }
    g_Vf[idx] = pack_h2(v[0], v[1]);
}

// ---------------- stage 1: P = structured low-rank projections (tf32 MMA, half2 fragment store) ----------------
#define S1_LDA 20
#define S1_LDW 68
__global__ __launch_bounds__(128) void stage1_kernel(
    const float* __restrict__ x, const float* __restrict__ h,
    const float* __restrict__ u_x, const float* __restrict__ u_h0,
    const float* __restrict__ u_h1) {
    __shared__ float As[128 * S1_LDA];
    __shared__ float Ws[16 * S1_LDW];

    int blk = blockIdx.y;
    int r0  = blockIdx.x * 128;
    const float* Aptr; const float* Wptr; int K; int pcol16;
    if      (blk == 0) { Aptr = x;       Wptr = u_x;            K = 1024; pcol16 = 0;  }
    else if (blk == 1) { Aptr = h;       Wptr = u_h0;           K = 512;  pcol16 = 4;  }
    else if (blk == 2) { Aptr = h + 512; Wptr = u_h1;           K = 512;  pcol16 = 8;  }
    else if (blk == 3) { Aptr = h + 512; Wptr = u_h0 + 512*64;  K = 512;  pcol16 = 16; }
    else               { Aptr = h;       Wptr = u_h1 + 512*64;  K = 512;  pcol16 = 20; }

    int t = threadIdx.x;
    int warp = t >> 5, lane = t & 31, g4 = lane >> 2, q = lane & 3;

    float acc[2][8][4];
#pragma unroll
    for (int i = 0; i < 2; i++)
#pragma unroll
        for (int j = 0; j < 8; j++)
#pragma unroll
            for (int l = 0; l < 4; l++) acc[i][j][l] = 0.f;

    int NK = K >> 4;
    float4 aR[4], wR[2];
    {
        const float* arow = Aptr + (size_t)(r0 + t) * 1024;
        aR[0] = *(const float4*)(arow + 0);  aR[1] = *(const float4*)(arow + 4);
        aR[2] = *(const float4*)(arow + 8);  aR[3] = *(const float4*)(arow + 12);
        wR[0] = *(const float4*)(Wptr + ((t >> 4)    ) * 64 + (t & 15) * 4);
        wR[1] = *(const float4*)(Wptr + ((t >> 4) + 8) * 64 + (t & 15) * 4);
    }

#pragma unroll 1
    for (int ks = 0; ks < NK; ks++) {
        __syncthreads();
        {
            float* ad = &As[t * S1_LDA];
            ad[0]  = tf32r(aR[0].x); ad[1]  = tf32r(aR[0].y); ad[2]  = tf32r(aR[0].z); ad[3]  = tf32r(aR[0].w);
            ad[4]  = tf32r(aR[1].x); ad[5]  = tf32r(aR[1].y); ad[6]  = tf32r(aR[1].z); ad[7]  = tf32r(aR[1].w);
            ad[8]  = tf32r(aR[2].x); ad[9]  = tf32r(aR[2].y); ad[10] = tf32r(aR[2].z); ad[11] = tf32r(aR[2].w);
            ad[12] = tf32r(aR[3].x); ad[13] = tf32r(aR[3].y); ad[14] = tf32r(aR[3].z); ad[15] = tf32r(aR[3].w);
            int wr = t >> 4, wc = (t & 15) * 4;
            float* w0 = &Ws[wr * S1_LDW + wc];
            w0[0] = tf32r(wR[0].x); w0[1] = tf32r(wR[0].y); w0[2] = tf32r(wR[0].z); w0[3] = tf32r(wR[0].w);
            float* w1 = &Ws[(wr + 8) * S1_LDW + wc];
            w1[0] = tf32r(wR[1].x); w1[1] = tf32r(wR[1].y); w1[2] = tf32r(wR[1].z); w1[3] = tf32r(wR[1].w);
        }
        __syncthreads();
        if (ks + 1 < NK) {
            int koff = (ks + 1) << 4;
            const float* arow = Aptr + (size_t)(r0 + t) * 1024 + koff;
            aR[0] = *(const float4*)(arow + 0);  aR[1] = *(const float4*)(arow + 4);
            aR[2] = *(const float4*)(arow + 8);  aR[3] = *(const float4*)(arow + 12);
            wR[0] = *(const float4*)(Wptr + (koff + (t >> 4)    ) * 64 + (t & 15) * 4);
            wR[1] = *(const float4*)(Wptr + (koff + (t >> 4) + 8) * 64 + (t & 15) * 4);
        }
#pragma unroll
        for (int kk = 0; kk < 2; kk++) {
            int kb = kk * 8;
            unsigned af[2][4], bf[8][2];
#pragma unroll
            for (int mt = 0; mt < 2; mt++) {
                int rr = warp * 32 + mt * 16 + g4;
                af[mt][0] = __float_as_uint(As[rr * S1_LDA + kb + q]);
                af[mt][1] = __float_as_uint(As[(rr + 8) * S1_LDA + kb + q]);
                af[mt][2] = __float_as_uint(As[rr * S1_LDA + kb + q + 4]);
                af[mt][3] = __float_as_uint(As[(rr + 8) * S1_LDA + kb + q + 4]);
            }
#pragma unroll
            for (int nt = 0; nt < 8; nt++) {
                bf[nt][0] = __float_as_uint(Ws[(kb + q) * S1_LDW + nt * 8 + g4]);
                bf[nt][1] = __float_as_uint(Ws[(kb + q + 4) * S1_LDW + nt * 8 + g4]);
            }
#pragma unroll
            for (int mt = 0; mt < 2; mt++)
#pragma unroll
                for (int nt = 0; nt < 8; nt++)
                    mma_tf32(acc[mt][nt], af[mt], bf[nt]);
        }
    }

    // ---- store P as A-fragment-ordered half2 ----
    // acc[mt][nt]: l0=[g4][2q], l1=[g4][2q+1], l2=[g4+8][2q], l3=[g4+8][2q+1]
    // -> (l0,l1) = reg (nt&1)*2, (l2,l3) = reg (nt&1)*2+1, lane unchanged
#pragma unroll
    for (int mt = 0; mt < 2; mt++) {
        int row16 = (r0 + warp * 32 + mt * 16) >> 4;
#pragma unroll
        for (int nt = 0; nt < 8; nt++) {
            int slice = pcol16 + (nt >> 1);
            unsigned p01 = pack_h2(acc[mt][nt][0], acc[mt][nt][1]);
            unsigned p23 = pack_h2(acc[mt][nt][2], acc[mt][nt][3]);
            size_t base = ((size_t)(row16 * 24 + slice) * 32 + lane) * 4 + (nt & 1) * 2;
            g_Pf[base]     = p01;
            g_Pf[base + 1] = p23;
            if (blk == 0) {                 // rx duplicated into group-1 block (+12 slices)
                g_Pf[base + 12 * 128]     = p01;
                g_Pf[base + 12 * 128 + 1] = p23;
            }
        }
    }
}

// ---------------- stage 2: fp16 m16n8k16, 128x128 tile, 4-stage cp.async, occ 2 ----------------
#define S2_STG_U 2048                       // uints per stage: A 1024 + B 1024
#define S2_DSMEM (4 * S2_STG_U * 4)         // 32 KB
#define S2_NCH   12                         // 192 / 16

__global__ __launch_bounds__(256, 2) void stage2_kernel(const float* __restrict__ cin,
                                                        float* __restrict__ out) {
    extern __shared__ unsigned sm[];

    int r0   = blockIdx.x * 128;
    int n128 = blockIdx.y;
    int s0   = n128 * 32;
    int g    = blockIdx.z;
    int t = threadIdx.x;
    int warp = t >> 5, lane = t & 31, g4 = lane >> 2, q = lane & 3;
    int wm = warp & 3, wn = warp >> 2;      // 4 m-warps x 2 n-warps; warp tile 32x64

    const unsigned* Abase = g_Pf + ((size_t)(r0 >> 4) * 24 + g * 12) * 128;
    const unsigned* Bbase = g_Vf + (size_t)(g * 16 + n128) * 12 * 1024;

    float acc[2][8][4];
#pragma unroll
    for (int i = 0; i < 2; i++)
#pragma unroll
        for (int j = 0; j < 8; j++)
#pragma unroll
            for (int l = 0; l < 4; l++) acc[i][j][l] = 0.f;

    auto issue = [&](int c) {
        if (c < S2_NCH) {
            unsigned* Ad = sm + (c & 3) * S2_STG_U;
            unsigned* Bd = Ad + 1024;
            int rbl = t >> 5, lo = t & 31;
            cp_async16u(Ad + rbl * 128 + lo * 4,
                        Abase + (size_t)rbl * (24 * 128) + c * 128 + lo * 4);
            cp_async16u(Bd + t * 4, Bbase + c * 1024 + t * 4);
        }
        asm volatile("cp.async.commit_group;" ::: "memory");
    };

    issue(0); issue(1); issue(2);

#pragma unroll 1
    for (int c = 0; c < S2_NCH; c++) {
        asm volatile("cp.async.wait_group 2;" ::: "memory");
        __syncthreads();
        unsigned* Aa = sm + (c & 3) * S2_STG_U;
        unsigned* Bb = Aa + 1024;

        unsigned af[2][4], bf[16];
#pragma unroll
        for (int mt = 0; mt < 2; mt++)
            *(uint4*)af[mt] = *(const uint4*)&Aa[(wm * 2 + mt) * 128 + lane * 4];
#pragma unroll
        for (int vg = 0; vg < 4; vg++)
            *(uint4*)&bf[vg * 4] = *(const uint4*)&Bb[wn * 512 + vg * 128 + lane * 4];

#pragma unroll
        for (int mt = 0; mt < 2; mt++)
#pragma unroll
            for (int nt = 0; nt < 8; nt++)
                mma_f16(acc[mt][nt], af[mt], &bf[nt * 2]);

        issue(c + 3);
    }

    // ---- fused epilogue: gate = nt>>1, s = s0 + wn*16 + (nt&1)*8 + 2q + e ----
    float* out_h = out;
    float* out_c = out + (size_t)B_ROWS * HDIM;
#pragma unroll
    for (int mt = 0; mt < 2; mt++) {
#pragma unroll
        for (int rh = 0; rh < 2; rh++) {
            int row = r0 + wm * 32 + mt * 16 + g4 + rh * 8;
#pragma unroll
            for (int sh = 0; sh < 2; sh++) {
                int sbase = s0 + wn * 16 + sh * 8 + 2 * q;
                float hv2[2], cv2[2];
                float2 cvv = *(const float2*)&cin[(size_t)row * HDIM + g * 512 + sbase];
                float cvin[2] = { cvv.x, cvv.y };
#pragma unroll
                for (int e = 0; e < 2; e++) {
                    int s = sbase + e;
                    int l = rh * 2 + e;
                    float fp = acc[mt][0 + sh][l] + g_bias[0 * 1024 + g * 512 + s];
                    float ip = acc[mt][2 + sh][l] + g_bias[1 * 1024 + g * 512 + s];
                    float np = acc[mt][4 + sh][l] + g_bias[2 * 1024 + g * 512 + s];
                    float op = acc[mt][6 + sh][l] + g_bias[3 * 1024 + g * 512 + s];
                    float fg = sigmoid_f(fp), ig = sigmoid_f(ip), og = sigmoid_f(op);
                    float ng = tanh_f(np);
                    float cn = fg * cvin[e] + ig * ng;
                    hv2[e] = og * tanh_f(cn);
                    cv2[e] = cn;
                }
                size_t off = (size_t)row * HDIM + g * 512 + sbase;
                *(float2*)&out_h[off] = make_float2(hv2[0], hv2[1]);
                *(float2*)&out_c[off] = make_float2(cv2[0], cv2[1]);
            }
        }
    }
}

// ---------------- launch ----------------
extern "C" void kernel_launch(void* const* d_in, const int* in_sizes, int n_in,
                              void* d_out, int out_size) {
    const float* x    = (const float*)d_in[0];
    const float* h    = (const float*)d_in[1];
    const float* c    = (const float*)d_in[2];
    const float* u_x  = (const float*)d_in[3];
    const float* v_x  = (const float*)d_in[4];
    const float* u_h0 = (const float*)d_in[5];
    const float* v_h0 = (const float*)d_in[6];
    const float* u_h1 = (const float*)d_in[7];
    const float* v_h1 = (const float*)d_in[8];
    const float* bx   = (const float*)d_in[9];
    const float* bh   = (const float*)d_in[10];

    cudaFuncSetAttribute(stage2_kernel, cudaFuncAttributeMaxDynamicSharedMemorySize, S2_DSMEM);

    prep_kernel<<<1536, 256>>>(v_x, v_h0, v_h1, bx, bh);
    stage1_kernel<<<dim3(64, 5), 128>>>(x, h, u_x, u_h0, u_h1);
    stage2_kernel<<<dim3(64, 16, 2), 256, S2_DSMEM>>>(c, (float*)d_out);
}

// round 10
// speedup vs baseline: 1.9934x; 1.3126x over previous
#include <cuda_runtime.h>
#include <cuda_fp16.h>

#define B_ROWS 8192
#define HDIM   1024
#define NACC   2048

// ---------------- device scratch (no allocations allowed) ----------------
// g_Pf: A-fragment-ordered half2 P.  uint idx = ((row16*24 + slice16)*32 + lane)*4 + reg
//   reg: 0={A[g4][2q],[2q+1]}, 1={A[g4+8][2q..]}, 2={A[g4][2q+8..]}, 3={A[g4+8][2q+8..]}
__device__ __align__(1024) unsigned g_Pf[512 * 24 * 128];          // 6.3 MB
// g_Vf: B-fragment-ordered half2 V.  uint idx = (((g*16+n128)*12 + k16)*2 + wn)*512 + vg*128 + lane*4 + j
__device__ __align__(1024) unsigned g_Vf[2 * 16 * 12 * 1024];      // 1.57 MB
// g_Wf: B-fragment-ordered half2 U (stage-1 weights).
//   idx = bt*WFS + ((k16*4 + wn)*2 + vg)*128 + lane*4 + j   (vg in 0..1)
//   r = vg*4+j: nt=r>>1, kreg=r&1; pair {W[k][n],W[k+1][n]}, k=k16*16+2q+kreg*8,
//   n = wn*WN + nt*8 + g4 with WN=16 (bt0) / 32 (bt1,2)
#define WFS 65536
__device__ __align__(1024) unsigned g_Wf[3 * WFS];                 // 786 KB
__device__ __align__(16)   float g_bias[4096];

#define VF_TOTAL (2 * 16 * 12 * 1024)
#define WF_TOTAL (3 * WFS)

// ---------------- helpers ----------------
__device__ __forceinline__ unsigned pack_h2(float a, float b) {
    __half2 h = __floats2half2_rn(a, b);
    return *reinterpret_cast<unsigned*>(&h);
}
__device__ __forceinline__ float sigmoid_f(float x) {
    float e; asm("ex2.approx.f32 %0, %1;" : "=f"(e) : "f"(-x * 1.4426950408889634f));
    float r; asm("rcp.approx.f32 %0, %1;" : "=f"(r) : "f"(1.0f + e));
    return r;
}
__device__ __forceinline__ float tanh_f(float x) {
    return fmaf(2.0f, sigmoid_f(2.0f * x), -1.0f);
}
__device__ __forceinline__ void mma_f16(float* d, const unsigned* a, const unsigned* b) {
    asm volatile(
        "mma.sync.aligned.m16n8k16.row.col.f32.f16.f16.f32 "
        "{%0,%1,%2,%3}, {%4,%5,%6,%7}, {%8,%9}, {%0,%1,%2,%3};\n"
        : "+f"(d[0]), "+f"(d[1]), "+f"(d[2]), "+f"(d[3])
        : "r"(a[0]), "r"(a[1]), "r"(a[2]), "r"(a[3]), "r"(b[0]), "r"(b[1]));
}

// ---------------- prep: g_Vf + g_Wf (fragment-ordered half2) + combined bias ----------------
__global__ void prep_kernel(const float* __restrict__ v_x, const float* __restrict__ v_h0,
                            const float* __restrict__ v_h1, const float* __restrict__ u_x,
                            const float* __restrict__ u_h0, const float* __restrict__ u_h1,
                            const float* __restrict__ bx, const float* __restrict__ bh) {
    int idx = blockIdx.x * 256 + threadIdx.x;
    if (idx < 4096) g_bias[idx] = bx[idx] + bh[idx];

    if (idx < VF_TOTAL) {
        int j    = idx & 3;
        int lane = (idx >> 2) & 31;
        int vg   = (idx >> 7) & 3;
        int rest = idx >> 9;
        int wn   = rest & 1;  rest >>= 1;
        int k16  = rest % 12; rest /= 12;
        int n128 = rest & 15;
        int g    = rest >> 4;

        int r    = vg * 4 + j;
        int nt   = r >> 1, kreg = r & 1;
        int g4   = lane >> 2, q = lane & 3;
        int k0   = k16 * 16 + 2 * q + kreg * 8;
        int gate = nt >> 1;
        int s    = n128 * 32 + wn * 16 + (nt & 1) * 8 + g4;

        float v[2];
#pragma unroll
        for (int e = 0; e < 2; e++) {
            int k = k0 + e;
            if (k < 64)       v[e] = v_x[(gate * 1024 + g * 512 + s) * 64 + k];
            else if (k < 128) v[e] = v_h0[(g * 64 + (k - 64)) * 2048 + gate * 512 + s];
            else              v[e] = v_h1[(g * 64 + (k - 128)) * 2048 + gate * 512 + s];
        }
        g_Vf[idx] = pack_h2(v[0], v[1]);
    } else if (idx < VF_TOTAL + WF_TOTAL) {
        int w    = idx - VF_TOTAL;
        int bt   = w / WFS;
        int rem  = w % WFS;
        int j    = rem & 3;
        int lane = (rem >> 2) & 31;
        int vg   = (rem >> 7) & 1;
        int wn   = (rem >> 8) & 3;
        int k16  = rem >> 10;

        int q = lane & 3, g4 = lane >> 2;
        int r = vg * 4 + j, nt = r >> 1, kreg = r & 1;
        int kb = k16 * 16 + 2 * q + kreg * 8;

        unsigned out = 0;
        bool ok = (bt == 0) ? (nt < 2) : (k16 < 32);
        if (ok) {
            int WN = (bt == 0) ? 16 : 32;
            int n  = wn * WN + nt * 8 + g4;
            float v[2];
#pragma unroll
            for (int e = 0; e < 2; e++) {
                int k = kb + e;
                if (bt == 0)      v[e] = u_x[k * 64 + n];
                else if (bt == 1) v[e] = (n < 64) ? u_h0[k * 64 + n]
                                                  : u_h1[(512 + k) * 64 + (n - 64)];
                else              v[e] = (n < 64) ? u_h1[k * 64 + n]
                                                  : u_h0[(512 + k) * 64 + (n - 64)];
            }
            out = pack_h2(v[0], v[1]);
        }
        g_Wf[w] = out;
    }
}

// ---------------- stage 1: barrier-free fp16 fragment GEMM -> g_Pf ----------------
// M=64 per CTA, 256 thr, 8 warps = 2 wm x 4 wn.
// bt0: x,        K=1024 (64 chunks), warp-N=16 (NT=2), cols 0..63  -> slices 0-3 (+dup 12-15)
// bt1: h[:,:512],K=512  (32 chunks), warp-N=32 (NT=4), cols 0..127 -> slices 4-7 / 20-23
// bt2: h[:,512:],K=512,                                 cols 0..127 -> slices 8-11 / 16-19
template<int NT, int NCH>
__device__ __forceinline__ void s1_body(const float* __restrict__ Aptr, int bt, int r0) {
    int t = threadIdx.x, warp = t >> 5, lane = t & 31, g4 = lane >> 2, q = lane & 3;
    int wm = warp >> 2, wn = warp & 3;

    const unsigned* Wp = g_Wf + bt * WFS + wn * 256 + lane * 4;

    float acc[2][NT][4];
#pragma unroll
    for (int i = 0; i < 2; i++)
#pragma unroll
        for (int jn = 0; jn < NT; jn++)
#pragma unroll
            for (int l = 0; l < 4; l++) acc[i][jn][l] = 0.f;

    const float* ar[2][2];
#pragma unroll
    for (int mt = 0; mt < 2; mt++) {
        int rb = r0 + wm * 32 + mt * 16;
        ar[mt][0] = Aptr + (size_t)(rb + g4) * 1024 + 2 * q;
        ar[mt][1] = Aptr + (size_t)(rb + g4 + 8) * 1024 + 2 * q;
    }

    float2 fa[2][4];
#pragma unroll
    for (int mt = 0; mt < 2; mt++) {
        fa[mt][0] = *(const float2*)(ar[mt][0]);
        fa[mt][1] = *(const float2*)(ar[mt][1]);
        fa[mt][2] = *(const float2*)(ar[mt][0] + 8);
        fa[mt][3] = *(const float2*)(ar[mt][1] + 8);
    }

#pragma unroll 1
    for (int c = 0; c < NCH; c++) {
        unsigned af[2][4];
#pragma unroll
        for (int mt = 0; mt < 2; mt++)
#pragma unroll
            for (int rr = 0; rr < 4; rr++)
                af[mt][rr] = pack_h2(fa[mt][rr].x, fa[mt][rr].y);

        if (c + 1 < NCH) {                       // prefetch next chunk's A
            int k0 = (c + 1) * 16;
#pragma unroll
            for (int mt = 0; mt < 2; mt++) {
                fa[mt][0] = *(const float2*)(ar[mt][0] + k0);
                fa[mt][1] = *(const float2*)(ar[mt][1] + k0);
                fa[mt][2] = *(const float2*)(ar[mt][0] + k0 + 8);
                fa[mt][3] = *(const float2*)(ar[mt][1] + k0 + 8);
            }
        }

        unsigned bf[NT * 2];
#pragma unroll
        for (int vg = 0; vg < NT / 2; vg++)
            *(uint4*)&bf[vg * 4] = *(const uint4*)(Wp + (size_t)c * 1024 + vg * 128);

#pragma unroll
        for (int mt = 0; mt < 2; mt++)
#pragma unroll
            for (int nt = 0; nt < NT; nt++)
                mma_f16(acc[mt][nt], af[mt], &bf[nt * 2]);
    }

    // ---- store A-fragment-ordered half2 into g_Pf ----
    const int WN = NT * 8;
#pragma unroll
    for (int mt = 0; mt < 2; mt++) {
        int row16 = (r0 + wm * 32 + mt * 16) >> 4;
#pragma unroll
        for (int nt = 0; nt < NT; nt++) {
            int col = wn * WN + nt * 8;
            int slice;
            if (bt == 0)      slice = col >> 4;
            else if (bt == 1) slice = (col < 64) ? 4 + (col >> 4) : 20 + ((col - 64) >> 4);
            else              slice = (col < 64) ? 8 + (col >> 4) : 16 + ((col - 64) >> 4);
            unsigned p01 = pack_h2(acc[mt][nt][0], acc[mt][nt][1]);
            unsigned p23 = pack_h2(acc[mt][nt][2], acc[mt][nt][3]);
            size_t base = ((size_t)(row16 * 24 + slice) * 32 + lane) * 4 + ((col >> 3) & 1) * 2;
            g_Pf[base]     = p01;
            g_Pf[base + 1] = p23;
            if (bt == 0) {                       // rx duplicated into group-1 block
                g_Pf[base + 12 * 128]     = p01;
                g_Pf[base + 12 * 128 + 1] = p23;
            }
        }
    }
}

__global__ __launch_bounds__(256, 2) void stage1_kernel(const float* __restrict__ x,
                                                        const float* __restrict__ h) {
    int bt = blockIdx.y;
    int r0 = blockIdx.x * 64;
    if (bt == 0)      s1_body<2, 64>(x, 0, r0);
    else if (bt == 1) s1_body<4, 32>(h, 1, r0);
    else              s1_body<4, 32>(h + 512, 2, r0);
}

// ---------------- stage 2: barrier-free fp16 fragment GEMM + fused gate epilogue ----------------
__global__ __launch_bounds__(256, 2) void stage2_kernel(const float* __restrict__ cin,
                                                        float* __restrict__ out) {
    int r0 = blockIdx.x * 128, n128 = blockIdx.y, g = blockIdx.z;
    int s0 = n128 * 32;
    int t = threadIdx.x, warp = t >> 5, lane = t & 31, g4 = lane >> 2, q = lane & 3;
    int wm = warp & 3, wn = warp >> 2;          // 4 m-warps x 2 n-warps; warp tile 32x64

    const unsigned* Ap = g_Pf + ((size_t)((r0 >> 4) + wm * 2) * 24 + g * 12) * 128 + lane * 4;
    const unsigned* Bp = g_Vf + (size_t)(g * 16 + n128) * 12 * 1024 + wn * 512 + lane * 4;

    float acc[2][8][4];
#pragma unroll
    for (int i = 0; i < 2; i++)
#pragma unroll
        for (int jn = 0; jn < 8; jn++)
#pragma unroll
            for (int l = 0; l < 4; l++) acc[i][jn][l] = 0.f;

    uint4 a0[2], a1[2], b0[4], b1[4];
    a0[0] = *(const uint4*)(Ap);
    a0[1] = *(const uint4*)(Ap + 24 * 128);
#pragma unroll
    for (int vg = 0; vg < 4; vg++) b0[vg] = *(const uint4*)(Bp + vg * 128);

#pragma unroll
    for (int c = 0; c < 12; c++) {
        uint4* ac = (c & 1) ? a1 : a0;
        uint4* an = (c & 1) ? a0 : a1;
        uint4* bc = (c & 1) ? b1 : b0;
        uint4* bn = (c & 1) ? b0 : b1;
        if (c < 11) {                            // prefetch next chunk (A + B)
            an[0] = *(const uint4*)(Ap + (size_t)(c + 1) * 128);
            an[1] = *(const uint4*)(Ap + (size_t)(c + 1) * 128 + 24 * 128);
#pragma unroll
            for (int vg = 0; vg < 4; vg++)
                bn[vg] = *(const uint4*)(Bp + (size_t)(c + 1) * 1024 + vg * 128);
        }
        const unsigned* af0 = (const unsigned*)&ac[0];
        const unsigned* af1 = (const unsigned*)&ac[1];
        const unsigned* bfp = (const unsigned*)bc;
#pragma unroll
        for (int nt = 0; nt < 8; nt++) {
            mma_f16(acc[0][nt], af0, bfp + nt * 2);
            mma_f16(acc[1][nt], af1, bfp + nt * 2);
        }
    }

    // ---- fused epilogue: gate = nt>>1, s = s0 + wn*16 + (nt&1)*8 + 2q + e ----
    float* out_h = out;
    float* out_c = out + (size_t)B_ROWS * HDIM;
#pragma unroll
    for (int mt = 0; mt < 2; mt++) {
#pragma unroll
        for (int rh = 0; rh < 2; rh++) {
            int row = r0 + wm * 32 + mt * 16 + g4 + rh * 8;
#pragma unroll
            for (int sh = 0; sh < 2; sh++) {
                int sbase = s0 + wn * 16 + sh * 8 + 2 * q;
                float hv2[2], cv2[2];
                float2 cvv = *(const float2*)&cin[(size_t)row * HDIM + g * 512 + sbase];
                float cvin[2] = { cvv.x, cvv.y };
#pragma unroll
                for (int e = 0; e < 2; e++) {
                    int s = sbase + e;
                    int l = rh * 2 + e;
                    float fp = acc[mt][0 + sh][l] + g_bias[0 * 1024 + g * 512 + s];
                    float ip = acc[mt][2 + sh][l] + g_bias[1 * 1024 + g * 512 + s];
                    float np = acc[mt][4 + sh][l] + g_bias[2 * 1024 + g * 512 + s];
                    float op = acc[mt][6 + sh][l] + g_bias[3 * 1024 + g * 512 + s];
                    float fg = sigmoid_f(fp), ig = sigmoid_f(ip), og = sigmoid_f(op);
                    float ng = tanh_f(np);
                    float cn = fg * cvin[e] + ig * ng;
                    hv2[e] = og * tanh_f(cn);
                    cv2[e] = cn;
                }
                size_t off = (size_t)row * HDIM + g * 512 + sbase;
                *(float2*)&out_h[off] = make_float2(hv2[0], hv2[1]);
                *(float2*)&out_c[off] = make_float2(cv2[0], cv2[1]);
            }
        }
    }
}

// ---------------- launch ----------------
extern "C" void kernel_launch(void* const* d_in, const int* in_sizes, int n_in,
                              void* d_out, int out_size) {
    const float* x    = (const float*)d_in[0];
    const float* h    = (const float*)d_in[1];
    const float* c    = (const float*)d_in[2];
    const float* u_x  = (const float*)d_in[3];
    const float* v_x  = (const float*)d_in[4];
    const float* u_h0 = (const float*)d_in[5];
    const float* v_h0 = (const float*)d_in[6];
    const float* u_h1 = (const float*)d_in[7];
    const float* v_h1 = (const float*)d_in[8];
    const float* bx   = (const float*)d_in[9];
    const float* bh   = (const float*)d_in[10];

    int prep_blocks = (VF_TOTAL + WF_TOTAL + 255) / 256;
    prep_kernel<<<prep_blocks, 256>>>(v_x, v_h0, v_h1, u_x, u_h0, u_h1, bx, bh);
    stage1_kernel<<<dim3(128, 3), 256>>>(x, h);
    stage2_kernel<<<dim3(64, 16, 2), 256>>>(c, (float*)d_out);
}

// round 11
// speedup vs baseline: 2.1203x; 1.0637x over previous
#include <cuda_runtime.h>
#include <cuda_fp16.h>

#define B_ROWS 8192
#define HDIM   1024
#define NACC   2048

// ---------------- device scratch (no allocations allowed) ----------------
// g_Pf: A-fragment-ordered half2 P.  uint idx = ((row16*24 + slice16)*32 + lane)*4 + reg
__device__ __align__(1024) unsigned g_Pf[512 * 24 * 128];          // 6.3 MB
// g_Vf: B-fragment-ordered half2 V.  idx = (((g*16+n128)*12 + k16)*2 + wn)*512 + vg*128 + lane*4 + j
__device__ __align__(1024) unsigned g_Vf[2 * 16 * 12 * 1024];      // 1.57 MB
// g_Wf: B-fragment-ordered half2 U (stage-1 weights).
#define WFS 65536
__device__ __align__(1024) unsigned g_Wf[3 * WFS];                 // 786 KB
// g_Xf / g_Hf: A-fragment-ordered half2 of x and h.
//   idx = ((row16*64 + k16)*32 + lane)*4 + reg ; reg j: row = row16*16 + g4 + (j&1)*8,
//   col pair = k16*16 + 2q + (j>>1)*8 + {0,1}
#define XH_TOTAL (512 * 64 * 128)   // 4,194,304 uints each
__device__ __align__(1024) unsigned g_Xf[XH_TOTAL];                // 16.8 MB
__device__ __align__(1024) unsigned g_Hf[XH_TOTAL];                // 16.8 MB
__device__ __align__(16)   float g_bias[4096];

#define VF_TOTAL (2 * 16 * 12 * 1024)
#define WF_TOTAL (3 * WFS)

// ---------------- helpers ----------------
__device__ __forceinline__ unsigned pack_h2(float a, float b) {
    __half2 h = __floats2half2_rn(a, b);
    return *reinterpret_cast<unsigned*>(&h);
}
__device__ __forceinline__ float sigmoid_f(float x) {
    float e; asm("ex2.approx.f32 %0, %1;" : "=f"(e) : "f"(-x * 1.4426950408889634f));
    float r; asm("rcp.approx.f32 %0, %1;" : "=f"(r) : "f"(1.0f + e));
    return r;
}
__device__ __forceinline__ float tanh_f(float x) {
    return fmaf(2.0f, sigmoid_f(2.0f * x), -1.0f);
}
__device__ __forceinline__ void mma_f16(float* d, const unsigned* a, const unsigned* b) {
    asm volatile(
        "mma.sync.aligned.m16n8k16.row.col.f32.f16.f16.f32 "
        "{%0,%1,%2,%3}, {%4,%5,%6,%7}, {%8,%9}, {%0,%1,%2,%3};\n"
        : "+f"(d[0]), "+f"(d[1]), "+f"(d[2]), "+f"(d[3])
        : "r"(a[0]), "r"(a[1]), "r"(a[2]), "r"(a[3]), "r"(b[0]), "r"(b[1]));
}

// ---------------- prep: g_Vf + g_Wf + g_Xf/g_Hf + combined bias ----------------
__global__ void prep_kernel(const float* __restrict__ v_x, const float* __restrict__ v_h0,
                            const float* __restrict__ v_h1, const float* __restrict__ u_x,
                            const float* __restrict__ u_h0, const float* __restrict__ u_h1,
                            const float* __restrict__ x,   const float* __restrict__ h,
                            const float* __restrict__ bx,  const float* __restrict__ bh) {
    int idx = blockIdx.x * 256 + threadIdx.x;
    if (idx < 4096) g_bias[idx] = bx[idx] + bh[idx];

    if (idx < VF_TOTAL) {
        int j    = idx & 3;
        int lane = (idx >> 2) & 31;
        int vg   = (idx >> 7) & 3;
        int rest = idx >> 9;
        int wn   = rest & 1;  rest >>= 1;
        int k16  = rest % 12; rest /= 12;
        int n128 = rest & 15;
        int g    = rest >> 4;

        int r    = vg * 4 + j;
        int nt   = r >> 1, kreg = r & 1;
        int g4   = lane >> 2, q = lane & 3;
        int k0   = k16 * 16 + 2 * q + kreg * 8;
        int gate = nt >> 1;
        int s    = n128 * 32 + wn * 16 + (nt & 1) * 8 + g4;

        float v[2];
#pragma unroll
        for (int e = 0; e < 2; e++) {
            int k = k0 + e;
            if (k < 64)       v[e] = v_x[(gate * 1024 + g * 512 + s) * 64 + k];
            else if (k < 128) v[e] = v_h0[(g * 64 + (k - 64)) * 2048 + gate * 512 + s];
            else              v[e] = v_h1[(g * 64 + (k - 128)) * 2048 + gate * 512 + s];
        }
        g_Vf[idx] = pack_h2(v[0], v[1]);
    } else if (idx < VF_TOTAL + WF_TOTAL) {
        int w    = idx - VF_TOTAL;
        int bt   = w / WFS;
        int rem  = w % WFS;
        int j    = rem & 3;
        int lane = (rem >> 2) & 31;
        int vg   = (rem >> 7) & 1;
        int wn   = (rem >> 8) & 3;
        int k16  = rem >> 10;

        int q = lane & 3, g4 = lane >> 2;
        int r = vg * 4 + j, nt = r >> 1, kreg = r & 1;
        int kb = k16 * 16 + 2 * q + kreg * 8;

        unsigned out = 0;
        bool ok = (bt == 0) ? (nt < 2) : (k16 < 32);
        if (ok) {
            int WN = (bt == 0) ? 16 : 32;
            int n  = wn * WN + nt * 8 + g4;
            float v[2];
#pragma unroll
            for (int e = 0; e < 2; e++) {
                int k = kb + e;
                if (bt == 0)      v[e] = u_x[k * 64 + n];
                else if (bt == 1) v[e] = (n < 64) ? u_h0[k * 64 + n]
                                                  : u_h1[(512 + k) * 64 + (n - 64)];
                else              v[e] = (n < 64) ? u_h1[k * 64 + n]
                                                  : u_h0[(512 + k) * 64 + (n - 64)];
            }
            out = pack_h2(v[0], v[1]);
        }
        g_Wf[w] = out;
    } else if (idx < VF_TOTAL + WF_TOTAL + 2 * XH_TOTAL) {
        int w2  = idx - VF_TOTAL - WF_TOTAL;
        int arr = w2 >> 22;                 // 0 = x, 1 = h
        int rem = w2 & (XH_TOTAL - 1);
        int j     = rem & 3;
        int lane  = (rem >> 2) & 31;
        int k16   = (rem >> 7) & 63;
        int row16 = rem >> 13;

        int g4 = lane >> 2, q = lane & 3;
        int row = row16 * 16 + g4 + (j & 1) * 8;
        int col = k16 * 16 + 2 * q + (j >> 1) * 8;
        const float* src = arr ? h : x;
        float2 v = *(const float2*)(src + (size_t)row * 1024 + col);
        unsigned out = pack_h2(v.x, v.y);
        if (arr) g_Hf[rem] = out; else g_Xf[rem] = out;
    }
}

// ---------------- stage 1: barrier-free fp16 fragment GEMM -> g_Pf ----------------
// M=64 per CTA, 256 thr, 8 warps = 2 wm x 4 wn. All fragments pre-built in gmem.
template<int NT, int NCH>
__device__ __forceinline__ void s1_body(const unsigned* __restrict__ Afrag, int bt, int r0) {
    int t = threadIdx.x, warp = t >> 5, lane = t & 31;
    int wm = warp >> 2, wn = warp & 3;

    const unsigned* Ap[2];
#pragma unroll
    for (int mt = 0; mt < 2; mt++) {
        int row16 = (r0 + wm * 32 + mt * 16) >> 4;
        Ap[mt] = Afrag + (size_t)row16 * (64 * 128) + lane * 4;
    }
    const unsigned* Wp = g_Wf + bt * WFS + wn * 256 + lane * 4;

    float acc[2][NT][4];
#pragma unroll
    for (int i = 0; i < 2; i++)
#pragma unroll
        for (int jn = 0; jn < NT; jn++)
#pragma unroll
            for (int l = 0; l < 4; l++) acc[i][jn][l] = 0.f;

    uint4 a0[2], a1[2], b0[NT / 2], b1[NT / 2];
#pragma unroll
    for (int mt = 0; mt < 2; mt++) a0[mt] = *(const uint4*)(Ap[mt]);
#pragma unroll
    for (int vg = 0; vg < NT / 2; vg++) b0[vg] = *(const uint4*)(Wp + vg * 128);

#pragma unroll
    for (int c = 0; c < NCH; c++) {
        uint4* ac = (c & 1) ? a1 : a0;
        uint4* an = (c & 1) ? a0 : a1;
        uint4* bc = (c & 1) ? b1 : b0;
        uint4* bn = (c & 1) ? b0 : b1;
        if (c + 1 < NCH) {
#pragma unroll
            for (int mt = 0; mt < 2; mt++)
                an[mt] = *(const uint4*)(Ap[mt] + (size_t)(c + 1) * 128);
#pragma unroll
            for (int vg = 0; vg < NT / 2; vg++)
                bn[vg] = *(const uint4*)(Wp + (size_t)(c + 1) * 1024 + vg * 128);
        }
        const unsigned* bfp = (const unsigned*)bc;
#pragma unroll
        for (int mt = 0; mt < 2; mt++)
#pragma unroll
            for (int nt = 0; nt < NT; nt++)
                mma_f16(acc[mt][nt], (const unsigned*)&ac[mt], bfp + nt * 2);
    }

    // ---- store A-fragment-ordered half2 into g_Pf ----
    const int WN = NT * 8;
#pragma unroll
    for (int mt = 0; mt < 2; mt++) {
        int row16 = (r0 + wm * 32 + mt * 16) >> 4;
#pragma unroll
        for (int nt = 0; nt < NT; nt++) {
            int col = wn * WN + nt * 8;
            int slice;
            if (bt == 0)      slice = col >> 4;
            else if (bt == 1) slice = (col < 64) ? 4 + (col >> 4) : 20 + ((col - 64) >> 4);
            else              slice = (col < 64) ? 8 + (col >> 4) : 16 + ((col - 64) >> 4);
            unsigned p01 = pack_h2(acc[mt][nt][0], acc[mt][nt][1]);
            unsigned p23 = pack_h2(acc[mt][nt][2], acc[mt][nt][3]);
            size_t base = ((size_t)(row16 * 24 + slice) * 32 + lane) * 4 + ((col >> 3) & 1) * 2;
            g_Pf[base]     = p01;
            g_Pf[base + 1] = p23;
            if (bt == 0) {                       // rx duplicated into group-1 block
                g_Pf[base + 12 * 128]     = p01;
                g_Pf[base + 12 * 128 + 1] = p23;
            }
        }
    }
}

__global__ __launch_bounds__(256, 2) void stage1_kernel() {
    int bt = blockIdx.y;
    int r0 = blockIdx.x * 64;
    if (bt == 0)      s1_body<2, 64>(g_Xf, 0, r0);
    else if (bt == 1) s1_body<4, 32>(g_Hf, 1, r0);
    else              s1_body<4, 32>(g_Hf + 32 * 128, 2, r0);
}

// ---------------- stage 2: barrier-free fp16 fragment GEMM + fused gate epilogue ----------------
__global__ __launch_bounds__(256, 2) void stage2_kernel(const float* __restrict__ cin,
                                                        float* __restrict__ out) {
    int r0 = blockIdx.x * 128, n128 = blockIdx.y, g = blockIdx.z;
    int s0 = n128 * 32;
    int t = threadIdx.x, warp = t >> 5, lane = t & 31, g4 = lane >> 2, q = lane & 3;
    int wm = warp & 3, wn = warp >> 2;          // 4 m-warps x 2 n-warps; warp tile 32x64

    const unsigned* Ap = g_Pf + ((size_t)((r0 >> 4) + wm * 2) * 24 + g * 12) * 128 + lane * 4;
    const unsigned* Bp = g_Vf + (size_t)(g * 16 + n128) * 12 * 1024 + wn * 512 + lane * 4;

    float acc[2][8][4];
#pragma unroll
    for (int i = 0; i < 2; i++)
#pragma unroll
        for (int jn = 0; jn < 8; jn++)
#pragma unroll
            for (int l = 0; l < 4; l++) acc[i][jn][l] = 0.f;

    uint4 a0[2], a1[2], b0[4], b1[4];
    a0[0] = *(const uint4*)(Ap);
    a0[1] = *(const uint4*)(Ap + 24 * 128);
#pragma unroll
    for (int vg = 0; vg < 4; vg++) b0[vg] = *(const uint4*)(Bp + vg * 128);

#pragma unroll
    for (int c = 0; c < 12; c++) {
        uint4* ac = (c & 1) ? a1 : a0;
        uint4* an = (c & 1) ? a0 : a1;
        uint4* bc = (c & 1) ? b1 : b0;
        uint4* bn = (c & 1) ? b0 : b1;
        if (c < 11) {                            // prefetch next chunk (A + B)
            an[0] = *(const uint4*)(Ap + (size_t)(c + 1) * 128);
            an[1] = *(const uint4*)(Ap + (size_t)(c + 1) * 128 + 24 * 128);
#pragma unroll
            for (int vg = 0; vg < 4; vg++)
                bn[vg] = *(const uint4*)(Bp + (size_t)(c + 1) * 1024 + vg * 128);
        }
        const unsigned* af0 = (const unsigned*)&ac[0];
        const unsigned* af1 = (const unsigned*)&ac[1];
        const unsigned* bfp = (const unsigned*)bc;
#pragma unroll
        for (int nt = 0; nt < 8; nt++) {
            mma_f16(acc[0][nt], af0, bfp + nt * 2);
            mma_f16(acc[1][nt], af1, bfp + nt * 2);
        }
    }

    // ---- fused epilogue: gate = nt>>1, s = s0 + wn*16 + (nt&1)*8 + 2q + e ----
    float* out_h = out;
    float* out_c = out + (size_t)B_ROWS * HDIM;
#pragma unroll
    for (int mt = 0; mt < 2; mt++) {
#pragma unroll
        for (int rh = 0; rh < 2; rh++) {
            int row = r0 + wm * 32 + mt * 16 + g4 + rh * 8;
#pragma unroll
            for (int sh = 0; sh < 2; sh++) {
                int sbase = s0 + wn * 16 + sh * 8 + 2 * q;
                float hv2[2], cv2[2];
                float2 cvv = *(const float2*)&cin[(size_t)row * HDIM + g * 512 + sbase];
                float cvin[2] = { cvv.x, cvv.y };
#pragma unroll
                for (int e = 0; e < 2; e++) {
                    int s = sbase + e;
                    int l = rh * 2 + e;
                    float fp = acc[mt][0 + sh][l] + g_bias[0 * 1024 + g * 512 + s];
                    float ip = acc[mt][2 + sh][l] + g_bias[1 * 1024 + g * 512 + s];
                    float np = acc[mt][4 + sh][l] + g_bias[2 * 1024 + g * 512 + s];
                    float op = acc[mt][6 + sh][l] + g_bias[3 * 1024 + g * 512 + s];
                    float fg = sigmoid_f(fp), ig = sigmoid_f(ip), og = sigmoid_f(op);
                    float ng = tanh_f(np);
                    float cn = fg * cvin[e] + ig * ng;
                    hv2[e] = og * tanh_f(cn);
                    cv2[e] = cn;
                }
                size_t off = (size_t)row * HDIM + g * 512 + sbase;
                *(float2*)&out_h[off] = make_float2(hv2[0], hv2[1]);
                *(float2*)&out_c[off] = make_float2(cv2[0], cv2[1]);
            }
        }
    }
}

// ---------------- launch ----------------
extern "C" void kernel_launch(void* const* d_in, const int* in_sizes, int n_in,
                              void* d_out, int out_size) {
    const float* x    = (const float*)d_in[0];
    const float* h    = (const float*)d_in[1];
    const float* c    = (const float*)d_in[2];
    const float* u_x  = (const float*)d_in[3];
    const float* v_x  = (const float*)d_in[4];
    const float* u_h0 = (const float*)d_in[5];
    const float* v_h0 = (const float*)d_in[6];
    const float* u_h1 = (const float*)d_in[7];
    const float* v_h1 = (const float*)d_in[8];
    const float* bx   = (const float*)d_in[9];
    const float* bh   = (const float*)d_in[10];

    int prep_total  = VF_TOTAL + WF_TOTAL + 2 * XH_TOTAL;
    int prep_blocks = (prep_total + 255) / 256;
    prep_kernel<<<prep_blocks, 256>>>(v_x, v_h0, v_h1, u_x, u_h0, u_h1, x, h, bx, bh);
    stage1_kernel<<<dim3(128, 3), 256>>>();
    stage2_kernel<<<dim3(64, 16, 2), 256>>>(c, (float*)d_out);
}

// round 13
// speedup vs baseline: 2.4470x; 1.1541x over previous
#include <cuda_runtime.h>
#include <cuda_fp16.h>

#define B_ROWS 8192
#define HDIM   1024
#define NACC   2048

// ---------------- device scratch (no allocations allowed) ----------------
// g_Pf: A-fragment-ordered half2 P.  uint idx = ((row16*24 + slice16)*32 + lane)*4 + reg
__device__ __align__(1024) unsigned g_Pf[512 * 24 * 128];          // 6.3 MB
// g_Vf: B-fragment-ordered half2 V.  idx = (((g*16+n128)*12 + k16)*2 + wn)*512 + vg*128 + lane*4 + j
__device__ __align__(1024) unsigned g_Vf[2 * 16 * 12 * 1024];      // 1.57 MB
// g_Wf: B-fragment-ordered half2 U (stage-1 weights).
#define WFS 65536
__device__ __align__(1024) unsigned g_Wf[3 * WFS];                 // 786 KB
// g_Xf / g_Hf: A-fragment-ordered half2 of x and h.
//   idx = ((row16*64 + k16)*32 + lane)*4 + reg ; reg j: row = row16*16 + g4 + (j&1)*8,
//   col pair = k16*16 + 2q + (j>>1)*8 + {0,1}
#define XH_TOTAL (512 * 64 * 128)   // 4,194,304 uints each
#define XH_QUADS (XH_TOTAL / 4)     // 1,048,576 uint4 per array
__device__ __align__(1024) unsigned g_Xf[XH_TOTAL];                // 16.8 MB
__device__ __align__(1024) unsigned g_Hf[XH_TOTAL];                // 16.8 MB
__device__ __align__(16)   float g_bias[4096];

#define VF_TOTAL (2 * 16 * 12 * 1024)
#define WF_TOTAL (3 * WFS)
#define PREP_TOTAL (VF_TOTAL + WF_TOTAL + 2 * XH_QUADS)

// ---------------- helpers ----------------
__device__ __forceinline__ unsigned pack_h2(float a, float b) {
    __half2 h = __floats2half2_rn(a, b);
    return *reinterpret_cast<unsigned*>(&h);
}
__device__ __forceinline__ float sigmoid_f(float x) {
    float e; asm("ex2.approx.f32 %0, %1;" : "=f"(e) : "f"(-x * 1.4426950408889634f));
    float r; asm("rcp.approx.f32 %0, %1;" : "=f"(r) : "f"(1.0f + e));
    return r;
}
__device__ __forceinline__ float tanh_f(float x) {
    return fmaf(2.0f, sigmoid_f(2.0f * x), -1.0f);
}
__device__ __forceinline__ void mma_f16(float* d, const unsigned* a, const unsigned* b) {
    asm volatile(
        "mma.sync.aligned.m16n8k16.row.col.f32.f16.f16.f32 "
        "{%0,%1,%2,%3}, {%4,%5,%6,%7}, {%8,%9}, {%0,%1,%2,%3};\n"
        : "+f"(d[0]), "+f"(d[1]), "+f"(d[2]), "+f"(d[3])
        : "r"(a[0]), "r"(a[1]), "r"(a[2]), "r"(a[3]), "r"(b[0]), "r"(b[1]));
}

// ---------------- prep: g_Vf + g_Wf + g_Xf/g_Hf + combined bias ----------------
__global__ void prep_kernel(const float* __restrict__ v_x, const float* __restrict__ v_h0,
                            const float* __restrict__ v_h1, const float* __restrict__ u_x,
                            const float* __restrict__ u_h0, const float* __restrict__ u_h1,
                            const float* __restrict__ x,   const float* __restrict__ h,
                            const float* __restrict__ bx,  const float* __restrict__ bh) {
    int idx = blockIdx.x * 256 + threadIdx.x;
    if (idx < 4096) g_bias[idx] = bx[idx] + bh[idx];

    if (idx < VF_TOTAL) {
        int j    = idx & 3;
        int lane = (idx >> 2) & 31;
        int vg   = (idx >> 7) & 3;
        int rest = idx >> 9;
        int wn   = rest & 1;  rest >>= 1;
        int k16  = rest % 12; rest /= 12;
        int n128 = rest & 15;
        int g    = rest >> 4;

        int r    = vg * 4 + j;
        int nt   = r >> 1, kreg = r & 1;
        int g4   = lane >> 2, q = lane & 3;
        int k0   = k16 * 16 + 2 * q + kreg * 8;
        int gate = nt >> 1;
        int s    = n128 * 32 + wn * 16 + (nt & 1) * 8 + g4;

        float v[2];
#pragma unroll
        for (int e = 0; e < 2; e++) {
            int k = k0 + e;
            if (k < 64)       v[e] = v_x[(gate * 1024 + g * 512 + s) * 64 + k];
            else if (k < 128) v[e] = v_h0[(g * 64 + (k - 64)) * 2048 + gate * 512 + s];
            else              v[e] = v_h1[(g * 64 + (k - 128)) * 2048 + gate * 512 + s];
        }
        g_Vf[idx] = pack_h2(v[0], v[1]);
    } else if (idx < VF_TOTAL + WF_TOTAL) {
        int w    = idx - VF_TOTAL;
        int bt   = w / WFS;
        int rem  = w % WFS;
        int j    = rem & 3;
        int lane = (rem >> 2) & 31;
        int vg   = (rem >> 7) & 1;
        int wn   = (rem >> 8) & 3;
        int k16  = rem >> 10;

        int q = lane & 3, g4 = lane >> 2;
        int r = vg * 4 + j, nt = r >> 1, kreg = r & 1;
        int kb = k16 * 16 + 2 * q + kreg * 8;

        unsigned out = 0;
        bool ok = (bt == 0) ? (nt < 2) : (k16 < 32);
        if (ok) {
            int WN = (bt == 0) ? 16 : 32;
            int n  = wn * WN + nt * 8 + g4;
            float v[2];
#pragma unroll
            for (int e = 0; e < 2; e++) {
                int k = kb + e;
                if (bt == 0)      v[e] = u_x[k * 64 + n];
                else if (bt == 1) v[e] = (n < 64) ? u_h0[k * 64 + n]
                                                  : u_h1[(512 + k) * 64 + (n - 64)];
                else              v[e] = (n < 64) ? u_h1[k * 64 + n]
                                                  : u_h0[(512 + k) * 64 + (n - 64)];
            }
            out = pack_h2(v[0], v[1]);
        }
        g_Wf[w] = out;
    } else if (idx < PREP_TOTAL) {
        // x/h -> A-fragment half2, one thread per uint4 (full lane fragment)
        int w2  = idx - VF_TOTAL - WF_TOTAL;
        int arr = w2 >> 20;                 // 0 = x, 1 = h  (XH_QUADS = 1<<20)
        int rem = w2 & (XH_QUADS - 1);
        int lane  = rem & 31;
        int k16   = (rem >> 5) & 63;
        int row16 = rem >> 11;

        int g4 = lane >> 2, q = lane & 3;
        const float* src = arr ? h : x;
        const float* base = src + (size_t)(row16 * 16 + g4) * 1024 + k16 * 16 + 2 * q;

        float2 v0 = *(const float2*)(base);                 // row g4,   cols 2q..2q+1
        float2 v1 = *(const float2*)(base + 8 * 1024);      // row g4+8
        float2 v2 = *(const float2*)(base + 8);             // row g4,   cols +8
        float2 v3 = *(const float2*)(base + 8 * 1024 + 8);  // row g4+8, cols +8

        uint4 out;
        out.x = pack_h2(v0.x, v0.y);
        out.y = pack_h2(v1.x, v1.y);
        out.z = pack_h2(v2.x, v2.y);
        out.w = pack_h2(v3.x, v3.y);
        unsigned* dst = arr ? g_Hf : g_Xf;
        *(uint4*)(dst + (size_t)rem * 4) = out;
    }
}

// ---------------- stage 1: barrier-free fp16 fragment GEMM -> g_Pf ----------------
// M=64 per CTA, 256 thr, 8 warps = 2 wm x 4 wn. All fragments pre-built in gmem.
template<int NT, int NCH>
__device__ __forceinline__ void s1_body(const unsigned* __restrict__ Afrag, int bt, int r0) {
    int t = threadIdx.x, warp = t >> 5, lane = t & 31;
    int wm = warp >> 2, wn = warp & 3;

    const unsigned* Ap[2];
#pragma unroll
    for (int mt = 0; mt < 2; mt++) {
        int row16 = (r0 + wm * 32 + mt * 16) >> 4;
        Ap[mt] = Afrag + (size_t)row16 * (64 * 128) + lane * 4;
    }
    const unsigned* Wp = g_Wf + bt * WFS + wn * 256 + lane * 4;

    float acc[2][NT][4];
#pragma unroll
    for (int i = 0; i < 2; i++)
#pragma unroll
        for (int jn = 0; jn < NT; jn++)
#pragma unroll
            for (int l = 0; l < 4; l++) acc[i][jn][l] = 0.f;

    uint4 a0[2], a1[2], b0[NT / 2], b1[NT / 2];
#pragma unroll
    for (int mt = 0; mt < 2; mt++) a0[mt] = *(const uint4*)(Ap[mt]);
#pragma unroll
    for (int vg = 0; vg < NT / 2; vg++) b0[vg] = *(const uint4*)(Wp + vg * 128);

#pragma unroll
    for (int c = 0; c < NCH; c++) {
        uint4* ac = (c & 1) ? a1 : a0;
        uint4* an = (c & 1) ? a0 : a1;
        uint4* bc = (c & 1) ? b1 : b0;
        uint4* bn = (c & 1) ? b0 : b1;
        if (c + 1 < NCH) {
#pragma unroll
            for (int mt = 0; mt < 2; mt++)
                an[mt] = *(const uint4*)(Ap[mt] + (size_t)(c + 1) * 128);
#pragma unroll
            for (int vg = 0; vg < NT / 2; vg++)
                bn[vg] = *(const uint4*)(Wp + (size_t)(c + 1) * 1024 + vg * 128);
        }
        const unsigned* bfp = (const unsigned*)bc;
#pragma unroll
        for (int mt = 0; mt < 2; mt++)
#pragma unroll
            for (int nt = 0; nt < NT; nt++)
                mma_f16(acc[mt][nt], (const unsigned*)&ac[mt], bfp + nt * 2);
    }

    // ---- store A-fragment-ordered half2 into g_Pf ----
    const int WN = NT * 8;
#pragma unroll
    for (int mt = 0; mt < 2; mt++) {
        int row16 = (r0 + wm * 32 + mt * 16) >> 4;
#pragma unroll
        for (int nt = 0; nt < NT; nt++) {
            int col = wn * WN + nt * 8;
            int slice;
            if (bt == 0)      slice = col >> 4;
            else if (bt == 1) slice = (col < 64) ? 4 + (col >> 4) : 20 + ((col - 64) >> 4);
            else              slice = (col < 64) ? 8 + (col >> 4) : 16 + ((col - 64) >> 4);
            unsigned p01 = pack_h2(acc[mt][nt][0], acc[mt][nt][1]);
            unsigned p23 = pack_h2(acc[mt][nt][2], acc[mt][nt][3]);
            size_t base = ((size_t)(row16 * 24 + slice) * 32 + lane) * 4 + ((col >> 3) & 1) * 2;
            g_Pf[base]     = p01;
            g_Pf[base + 1] = p23;
            if (bt == 0) {                       // rx duplicated into group-1 block
                g_Pf[base + 12 * 128]     = p01;
                g_Pf[base + 12 * 128 + 1] = p23;
            }
        }
    }
}

__global__ __launch_bounds__(256, 2) void stage1_kernel() {
    int bt = blockIdx.y;
    int r0 = blockIdx.x * 64;
    if (bt == 0)      s1_body<2, 64>(g_Xf, 0, r0);
    else if (bt == 1) s1_body<4, 32>(g_Hf, 1, r0);
    else              s1_body<4, 32>(g_Hf + 32 * 128, 2, r0);
}

// ---------------- stage 2: barrier-free fp16 fragment GEMM + fused gate epilogue ----------------
__global__ __launch_bounds__(256, 2) void stage2_kernel(const float* __restrict__ cin,
                                                        float* __restrict__ out) {
    int r0 = blockIdx.x * 128, n128 = blockIdx.y, g = blockIdx.z;
    int s0 = n128 * 32;
    int t = threadIdx.x, warp = t >> 5, lane = t & 31, g4 = lane >> 2, q = lane & 3;
    int wm = warp & 3, wn = warp >> 2;          // 4 m-warps x 2 n-warps; warp tile 32x64

    const unsigned* Ap = g_Pf + ((size_t)((r0 >> 4) + wm * 2) * 24 + g * 12) * 128 + lane * 4;
    const unsigned* Bp = g_Vf + (size_t)(g * 16 + n128) * 12 * 1024 + wn * 512 + lane * 4;

    float acc[2][8][4];
#pragma unroll
    for (int i = 0; i < 2; i++)
#pragma unroll
        for (int jn = 0; jn < 8; jn++)
#pragma unroll
            for (int l = 0; l < 4; l++) acc[i][jn][l] = 0.f;

    uint4 a0[2], a1[2], b0[4], b1[4];
    a0[0] = *(const uint4*)(Ap);
    a0[1] = *(const uint4*)(Ap + 24 * 128);
#pragma unroll
    for (int vg = 0; vg < 4; vg++) b0[vg] = *(const uint4*)(Bp + vg * 128);

#pragma unroll
    for (int c = 0; c < 12; c++) {
        uint4* ac = (c & 1) ? a1 : a0;
        uint4* an = (c & 1) ? a0 : a1;
        uint4* bc = (c & 1) ? b1 : b0;
        uint4* bn = (c & 1) ? b0 : b1;
        if (c < 11) {                            // prefetch next chunk (A + B)
            an[0] = *(const uint4*)(Ap + (size_t)(c + 1) * 128);
            an[1] = *(const uint4*)(Ap + (size_t)(c + 1) * 128 + 24 * 128);
#pragma unroll
            for (int vg = 0; vg < 4; vg++)
                bn[vg] = *(const uint4*)(Bp + (size_t)(c + 1) * 1024 + vg * 128);
        }
        const unsigned* af0 = (const unsigned*)&ac[0];
        const unsigned* af1 = (const unsigned*)&ac[1];
        const unsigned* bfp = (const unsigned*)bc;
#pragma unroll
        for (int nt = 0; nt < 8; nt++) {
            mma_f16(acc[0][nt], af0, bfp + nt * 2);
            mma_f16(acc[1][nt], af1, bfp + nt * 2);
        }
    }

    // ---- fused epilogue: gate = nt>>1, s = s0 + wn*16 + (nt&1)*8 + 2q + e ----
    float* out_h = out;
    float* out_c = out + (size_t)B_ROWS * HDIM;
#pragma unroll
    for (int mt = 0; mt < 2; mt++) {
#pragma unroll
        for (int rh = 0; rh < 2; rh++) {
            int row = r0 + wm * 32 + mt * 16 + g4 + rh * 8;
#pragma unroll
            for (int sh = 0; sh < 2; sh++) {
                int sbase = s0 + wn * 16 + sh * 8 + 2 * q;
                float hv2[2], cv2[2];
                float2 cvv = *(const float2*)&cin[(size_t)row * HDIM + g * 512 + sbase];
                float cvin[2] = { cvv.x, cvv.y };
#pragma unroll
                for (int e = 0; e < 2; e++) {
                    int s = sbase + e;
                    int l = rh * 2 + e;
                    float fp = acc[mt][0 + sh][l] + g_bias[0 * 1024 + g * 512 + s];
                    float ip = acc[mt][2 + sh][l] + g_bias[1 * 1024 + g * 512 + s];
                    float np = acc[mt][4 + sh][l] + g_bias[2 * 1024 + g * 512 + s];
                    float op = acc[mt][6 + sh][l] + g_bias[3 * 1024 + g * 512 + s];
                    float fg = sigmoid_f(fp), ig = sigmoid_f(ip), og = sigmoid_f(op);
                    float ng = tanh_f(np);
                    float cn = fg * cvin[e] + ig * ng;
                    hv2[e] = og * tanh_f(cn);
                    cv2[e] = cn;
                }
                size_t off = (size_t)row * HDIM + g * 512 + sbase;
                *(float2*)&out_h[off] = make_float2(hv2[0], hv2[1]);
                *(float2*)&out_c[off] = make_float2(cv2[0], cv2[1]);
            }
        }
    }
}

// ---------------- launch ----------------
extern "C" void kernel_launch(void* const* d_in, const int* in_sizes, int n_in,
                              void* d_out, int out_size) {
    const float* x    = (const float*)d_in[0];
    const float* h    = (const float*)d_in[1];
    const float* c    = (const float*)d_in[2];
    const float* u_x  = (const float*)d_in[3];
    const float* v_x  = (const float*)d_in[4];
    const float* u_h0 = (const float*)d_in[5];
    const float* v_h0 = (const float*)d_in[6];
    const float* u_h1 = (const float*)d_in[7];
    const float* v_h1 = (const float*)d_in[8];
    const float* bx   = (const float*)d_in[9];
    const float* bh   = (const float*)d_in[10];

    int prep_blocks = (PREP_TOTAL + 255) / 256;
    prep_kernel<<<prep_blocks, 256>>>(v_x, v_h0, v_h1, u_x, u_h0, u_h1, x, h, bx, bh);
    stage1_kernel<<<dim3(128, 3), 256>>>();
    stage2_kernel<<<dim3(64, 16, 2), 256>>>(c, (float*)d_out);
}